// round 1
// baseline (speedup 1.0000x reference)
#include <cuda_runtime.h>

#define NUx 100000
#define NIx 100000
#define NEx 600000
#define D   128
#define DO  16

// ---------------- device scratch (no allocation allowed) ----------------
__device__ float g_agg_uu[NUx * D];   // mean-agg of embed_user over (src_uu,dst_uu)
__device__ float g_agg_iu[NUx * D];   // mean-agg of embed_item over (src_iu,dst_iu)
__device__ float g_agg_ui[NIx * D];   // mean-agg of embed_user over (src_ui,dst_ui)
__device__ float g_h_user[NUx * D];
__device__ float g_h_item[NIx * D];
__device__ float g_p_user[NUx * DO];
__device__ float g_p_item[NIx * DO];
__device__ float g_s1[NUx * DO];
__device__ float g_s2[NUx * DO];
__device__ int   g_deg_uu[NUx];
__device__ int   g_deg_iu[NUx];
__device__ int   g_deg_ui[NIx];

// ---------------- helpers ----------------
typedef unsigned long long u64t;

__device__ __forceinline__ void red_add4(float* p, float4 v) {
    asm volatile("red.global.add.v4.f32 [%0], {%1, %2, %3, %4};"
                 :: "l"(p), "f"(v.x), "f"(v.y), "f"(v.z), "f"(v.w) : "memory");
}
__device__ __forceinline__ u64t pk2(float lo, float hi) {
    u64t r; asm("mov.b64 %0, {%1, %2};" : "=l"(r) : "f"(lo), "f"(hi)); return r;
}
__device__ __forceinline__ void fma2(u64t& d, u64t a, u64t b) {
    asm("fma.rn.f32x2 %0, %1, %2, %0;" : "+l"(d) : "l"(a), "l"(b));
}
__device__ __forceinline__ float2 up2(u64t v) {
    float lo, hi; asm("mov.b64 {%0, %1}, %2;" : "=f"(lo), "=f"(hi) : "l"(v));
    return make_float2(lo, hi);
}

// ---------------- kernels ----------------

// Zero all accumulators + degrees (d_out is fully overwritten by k_final).
__global__ void k_zero() {
    int t = blockIdx.x * blockDim.x + threadIdx.x;
    int stride = gridDim.x * blockDim.x;
    float4 z = make_float4(0.f, 0.f, 0.f, 0.f);
    for (int i = t; i < NUx * (D / 4); i += stride) {
        ((float4*)g_agg_uu)[i] = z;
        ((float4*)g_agg_iu)[i] = z;
        ((float4*)g_agg_ui)[i] = z;
    }
    for (int i = t; i < NUx * (DO / 4); i += stride) {
        ((float4*)g_s1)[i] = z;
        ((float4*)g_s2)[i] = z;
    }
    for (int i = t; i < NUx; i += stride) {
        g_deg_uu[i] = 0; g_deg_iu[i] = 0; g_deg_ui[i] = 0;
    }
}

__global__ void k_degree(const int* __restrict__ duu, const int* __restrict__ dui,
                         const int* __restrict__ diu) {
    int e = blockIdx.x * blockDim.x + threadIdx.x;
    if (e < NEx) {
        atomicAdd(&g_deg_uu[duu[e]], 1);
        atomicAdd(&g_deg_ui[dui[e]], 1);
        atomicAdd(&g_deg_iu[diu[e]], 1);
    }
}

// Layer-0 scatter: raw 128-d embeddings, one warp per edge (32 x float4).
// blockIdx.y = edge type (0:uu, 1:ui, 2:iu). gridDim.x * 256 == NE*32 exactly.
__global__ void k_scatter0(const float* __restrict__ eu, const float* __restrict__ ei,
                           const int* __restrict__ suu, const int* __restrict__ duu,
                           const int* __restrict__ sui, const int* __restrict__ dui,
                           const int* __restrict__ siu, const int* __restrict__ diu) {
    int idx  = blockIdx.x * blockDim.x + threadIdx.x;   // 0 .. NE*32-1
    int lane = idx & 31;
    int e    = idx >> 5;
    int et   = blockIdx.y;
    const float* emb; const int* s; const int* d; float* agg;
    if (et == 0)      { emb = eu; s = suu; d = duu; agg = g_agg_uu; }
    else if (et == 1) { emb = eu; s = sui; d = dui; agg = g_agg_ui; }
    else              { emb = ei; s = siu; d = diu; agg = g_agg_iu; }
    int sn = s[e], dn = d[e];
    float4 v = ((const float4*)emb)[(size_t)sn * 32 + lane];
    red_add4(&agg[((size_t)dn * 32 + lane) * 4], v);
}

// Layer-0 fused: H = relu( (A0/deg0)@W0 + b0*(deg0>0)  [ + (A1/deg1)@Wb + bb*(deg1>0) ] )
// Block: 256 threads, 32 nodes, all 128 output cols. Packed f32x2 FMA.
template <int TWO>
__global__ void __launch_bounds__(256) k_gemm_l0(
    const float* __restrict__ A0, const int* __restrict__ dg0,
    const float* __restrict__ W0, const float* __restrict__ b0v,
    const float* __restrict__ A1, const int* __restrict__ dg1,
    const float* __restrict__ Wb, const float* __restrict__ bbv,
    float* __restrict__ H) {
    __shared__ float sa0[32][D];
    __shared__ float sa1[TWO ? 32 : 1][TWO ? D : 1];
    __shared__ float sinv0[32], smk0[32], sinv1[32], smk1[32];
    const int tid  = threadIdx.x;
    const int base = blockIdx.x * 32;

    if (tid < 32) {
        int d0 = dg0[base + tid];
        sinv0[tid] = 1.0f / (float)max(d0, 1);
        smk0[tid]  = d0 > 0 ? 1.0f : 0.0f;
        if (TWO) {
            int d1 = dg1[base + tid];
            sinv1[tid] = 1.0f / (float)max(d1, 1);
            smk1[tid]  = d1 > 0 ? 1.0f : 0.0f;
        }
    }
    __syncthreads();

#pragma unroll
    for (int i = 0; i < 4; i++) {
        int f = tid + i * 256;          // 0..1023 float4s
        int r = f >> 5, c = f & 31;
        float4 v = ((const float4*)A0)[(size_t)(base + r) * 32 + c];
        float s = sinv0[r];
        v.x *= s; v.y *= s; v.z *= s; v.w *= s;
        *(float4*)&sa0[r][c * 4] = v;
        if (TWO) {
            float4 u = ((const float4*)A1)[(size_t)(base + r) * 32 + c];
            float t = sinv1[r];
            u.x *= t; u.y *= t; u.z *= t; u.w *= t;
            *(float4*)&sa1[r][c * 4] = u;
        }
    }
    __syncthreads();

    const int jt = tid & 31, mt = tid >> 5;
    float4 bb0 = ((const float4*)b0v)[jt];
    float4 bb1 = TWO ? ((const float4*)bbv)[jt] : make_float4(0.f, 0.f, 0.f, 0.f);

    u64t acc[4][2];
#pragma unroll
    for (int i = 0; i < 4; i++) {
        float m0 = smk0[mt * 4 + i];
        float m1 = TWO ? smk1[mt * 4 + i] : 0.f;
        acc[i][0] = pk2(bb0.x * m0 + bb1.x * m1, bb0.y * m0 + bb1.y * m1);
        acc[i][1] = pk2(bb0.z * m0 + bb1.z * m1, bb0.w * m0 + bb1.w * m1);
    }

    const float4* W0f = (const float4*)W0;
    const float4* Wbf = (const float4*)Wb;
#pragma unroll 4
    for (int k = 0; k < D; k++) {
        float4 w0 = W0f[k * 32 + jt];
        u64t w0a = pk2(w0.x, w0.y), w0b = pk2(w0.z, w0.w);
        u64t w1a = 0, w1b = 0;
        if (TWO) {
            float4 w1 = Wbf[k * 32 + jt];
            w1a = pk2(w1.x, w1.y); w1b = pk2(w1.z, w1.w);
        }
#pragma unroll
        for (int i = 0; i < 4; i++) {
            float a0 = sa0[mt * 4 + i][k];
            u64t a0p = pk2(a0, a0);
            fma2(acc[i][0], a0p, w0a);
            fma2(acc[i][1], a0p, w0b);
            if (TWO) {
                float a1 = sa1[mt * 4 + i][k];
                u64t a1p = pk2(a1, a1);
                fma2(acc[i][0], a1p, w1a);
                fma2(acc[i][1], a1p, w1b);
            }
        }
    }

#pragma unroll
    for (int i = 0; i < 4; i++) {
        float2 x = up2(acc[i][0]);
        float2 y = up2(acc[i][1]);
        float4 o = make_float4(fmaxf(x.x, 0.f), fmaxf(x.y, 0.f),
                               fmaxf(y.x, 0.f), fmaxf(y.y, 0.f));
        ((float4*)H)[(size_t)(base + mt * 4 + i) * 32 + jt] = o;
    }
}

// Layer-1 projection: P[N,16] = H[N,128] @ W1[128,16] + b1. 64 nodes/block.
__global__ void __launch_bounds__(256) k_proj(const float* __restrict__ Hm,
                                              const float* __restrict__ W1,
                                              const float* __restrict__ b1,
                                              float* __restrict__ P, int N) {
    __shared__ float sh[64][132];
    __shared__ float sw[D * DO];
    int tid  = threadIdx.x;
    int base = blockIdx.x * 64;
#pragma unroll
    for (int i = 0; i < 2; i++) {
        int f = tid + i * 256;          // 512 float4s of W1
        ((float4*)sw)[f] = ((const float4*)W1)[f];
    }
#pragma unroll
    for (int i = 0; i < 8; i++) {
        int f = tid + i * 256;          // 2048 float4s of H tile
        int r = f >> 5, c = f & 31;
        int n = base + r; if (n >= N) n = N - 1;
        float4 v = ((const float4*)Hm)[(size_t)n * 32 + c];
        *(float4*)&sh[r][c * 4] = v;
    }
    __syncthreads();
    int m = tid >> 2, q = tid & 3;
    float4 bb = ((const float4*)b1)[q];
    float a0 = bb.x, a1 = bb.y, a2 = bb.z, a3 = bb.w;
#pragma unroll 8
    for (int k = 0; k < D; k++) {
        float hk = sh[m][k];
        float4 w = ((float4*)sw)[k * 4 + q];
        a0 += hk * w.x; a1 += hk * w.y; a2 += hk * w.z; a3 += hk * w.w;
    }
    int n = base + m;
    if (n < N) ((float4*)P)[n * 4 + q] = make_float4(a0, a1, a2, a3);
}

// Layer-1 scatter: 16-d messages, 4 lanes/edge. blockIdx.y: 0 -> p_user/uu->S1, 1 -> p_item/iu->S2
__global__ void k_scatter1(const int* __restrict__ suu, const int* __restrict__ duu,
                           const int* __restrict__ siu, const int* __restrict__ diu) {
    int idx  = blockIdx.x * blockDim.x + threadIdx.x;   // 0 .. NE*4-1
    int lane = idx & 3;
    int e    = idx >> 2;
    const float* P; const int* s; const int* d; float* S;
    if (blockIdx.y == 0) { P = g_p_user; s = suu; d = duu; S = g_s1; }
    else                 { P = g_p_item; s = siu; d = diu; S = g_s2; }
    int sn = s[e], dn = d[e];
    float4 v = ((const float4*)P)[(size_t)sn * 4 + lane];
    red_add4(&S[((size_t)dn * 4 + lane) * 4], v);
}

__global__ void k_final(float* __restrict__ out) {
    int idx = blockIdx.x * blockDim.x + threadIdx.x;    // NU*4 float4s
    if (idx >= NUx * 4) return;
    int n = idx >> 2;
    float i1 = 1.0f / (float)max(g_deg_uu[n], 1);
    float i2 = 1.0f / (float)max(g_deg_iu[n], 1);
    float4 a = ((float4*)g_s1)[idx];
    float4 b = ((float4*)g_s2)[idx];
    ((float4*)out)[idx] = make_float4(a.x * i1 + b.x * i2, a.y * i1 + b.y * i2,
                                      a.z * i1 + b.z * i2, a.w * i1 + b.w * i2);
}

// ---------------- launch ----------------
extern "C" void kernel_launch(void* const* d_in, const int* in_sizes, int n_in,
                              void* d_out, int out_size) {
    const float* embed_user = (const float*)d_in[0];
    const float* embed_item = (const float*)d_in[1];
    const int* src_uu = (const int*)d_in[2];
    const int* dst_uu = (const int*)d_in[3];
    const int* src_ui = (const int*)d_in[4];
    const int* dst_ui = (const int*)d_in[5];
    const int* src_iu = (const int*)d_in[6];
    const int* dst_iu = (const int*)d_in[7];
    const float* W0_uu = (const float*)d_in[8];
    const float* b0_uu = (const float*)d_in[9];
    const float* W0_ui = (const float*)d_in[10];
    const float* b0_ui = (const float*)d_in[11];
    const float* W0_iu = (const float*)d_in[12];
    const float* b0_iu = (const float*)d_in[13];
    const float* W1_uu = (const float*)d_in[14];
    const float* b1_uu = (const float*)d_in[15];
    const float* W1_iu = (const float*)d_in[18];
    const float* b1_iu = (const float*)d_in[19];

    float *agg_uu, *agg_iu, *agg_ui, *h_user, *h_item, *p_user, *p_item;
    int *dg_uu, *dg_iu, *dg_ui;
    cudaGetSymbolAddress((void**)&agg_uu, g_agg_uu);
    cudaGetSymbolAddress((void**)&agg_iu, g_agg_iu);
    cudaGetSymbolAddress((void**)&agg_ui, g_agg_ui);
    cudaGetSymbolAddress((void**)&h_user, g_h_user);
    cudaGetSymbolAddress((void**)&h_item, g_h_item);
    cudaGetSymbolAddress((void**)&p_user, g_p_user);
    cudaGetSymbolAddress((void**)&p_item, g_p_item);
    cudaGetSymbolAddress((void**)&dg_uu, g_deg_uu);
    cudaGetSymbolAddress((void**)&dg_iu, g_deg_iu);
    cudaGetSymbolAddress((void**)&dg_ui, g_deg_ui);

    k_zero<<<2048, 256>>>();
    k_degree<<<(NEx + 255) / 256, 256>>>(dst_uu, dst_ui, dst_iu);

    dim3 g0(NEx * 32 / 256, 3);
    k_scatter0<<<g0, 256>>>(embed_user, embed_item,
                            src_uu, dst_uu, src_ui, dst_ui, src_iu, dst_iu);

    // h_user = relu(agg_uu/d @ W0_uu + b0_uu*m + agg_iu/d @ W0_iu + b0_iu*m)
    k_gemm_l0<1><<<NUx / 32, 256>>>(agg_uu, dg_uu, W0_uu, b0_uu,
                                    agg_iu, dg_iu, W0_iu, b0_iu, h_user);
    // h_item = relu(agg_ui/d @ W0_ui + b0_ui*m)
    k_gemm_l0<0><<<NIx / 32, 256>>>(agg_ui, dg_ui, W0_ui, b0_ui,
                                    (const float*)0, (const int*)0,
                                    (const float*)0, (const float*)0, h_item);

    k_proj<<<(NUx + 63) / 64, 256>>>(h_user, W1_uu, b1_uu, p_user, NUx);
    k_proj<<<(NIx + 63) / 64, 256>>>(h_item, W1_iu, b1_iu, p_item, NIx);

    dim3 g1(NEx * 4 / 256, 2);
    k_scatter1<<<g1, 256>>>(src_uu, dst_uu, src_iu, dst_iu);

    k_final<<<(NUx * 4 + 255) / 256, 256>>>((float*)d_out);
}

// round 2
// speedup vs baseline: 1.1799x; 1.1799x over previous
#include <cuda_runtime.h>

#define NUx 100000
#define NIx 100000
#define NEx 600000
#define D   128
#define DO  16
#define NB  391           // ceil(100000/256)
#define EB  2344          // ceil(600000/256)

// etype ids: 0 = uu (dst user, src user), 1 = ui (dst item, src user), 2 = iu (dst user, src item)
__device__ int g_deg[3][NUx];
__device__ int g_cur[3][NUx];
__device__ int g_rp[3][NUx + 1];
__device__ int g_col[3][NEx];
__device__ int g_bsum[3][512];
__device__ float g_h_user[NUx * D];
__device__ float g_h_item[NIx * D];
__device__ float g_p_user[NUx * DO];
__device__ float g_p_item[NIx * DO];

typedef unsigned long long u64t;

__device__ __forceinline__ u64t pk2(float lo, float hi) {
    u64t r; asm("mov.b64 %0, {%1, %2};" : "=l"(r) : "f"(lo), "f"(hi)); return r;
}
__device__ __forceinline__ void fma2(u64t& d, u64t a, u64t b) {
    asm("fma.rn.f32x2 %0, %1, %2, %0;" : "+l"(d) : "l"(a), "l"(b));
}
__device__ __forceinline__ float2 up2(u64t v) {
    float lo, hi; asm("mov.b64 {%0, %1}, %2;" : "=f"(lo), "=f"(hi) : "l"(v));
    return make_float2(lo, hi);
}

// ---------------- CSR build ----------------

__global__ void k_zero_small() {
    int i = blockIdx.x * blockDim.x + threadIdx.x;
    if (i < NUx) {
#pragma unroll
        for (int y = 0; y < 3; y++) { g_deg[y][i] = 0; g_cur[y][i] = 0; }
    }
}

__global__ void k_degree(const int* __restrict__ duu, const int* __restrict__ dui,
                         const int* __restrict__ diu) {
    int e = blockIdx.x * blockDim.x + threadIdx.x;
    if (e < NEx) {
        atomicAdd(&g_deg[0][duu[e]], 1);
        atomicAdd(&g_deg[1][dui[e]], 1);
        atomicAdd(&g_deg[2][diu[e]], 1);
    }
}

// Per-block exclusive scan; block totals to g_bsum.
__global__ void k_scan1() {
    __shared__ int s[256];
    int y = blockIdx.y;
    int t = threadIdx.x;
    int i = blockIdx.x * 256 + t;
    int v = (i < NUx) ? g_deg[y][i] : 0;
    s[t] = v;
    __syncthreads();
#pragma unroll
    for (int off = 1; off < 256; off <<= 1) {
        int x = (t >= off) ? s[t - off] : 0;
        __syncthreads();
        s[t] += x;
        __syncthreads();
    }
    if (i < NUx) g_rp[y][i] = s[t] - v;       // local exclusive
    if (t == 255) g_bsum[y][blockIdx.x] = s[255];
}

// Scan block sums (one block of 512 per etype).
__global__ void k_scan2() {
    __shared__ int s[512];
    int y = blockIdx.x;
    int t = threadIdx.x;
    int v = (t < NB) ? g_bsum[y][t] : 0;
    s[t] = v;
    __syncthreads();
#pragma unroll
    for (int off = 1; off < 512; off <<= 1) {
        int x = (t >= off) ? s[t - off] : 0;
        __syncthreads();
        s[t] += x;
        __syncthreads();
    }
    if (t < NB) g_bsum[y][t] = s[t] - v;      // exclusive block offsets
}

__global__ void k_scan3() {
    int y = blockIdx.y;
    int i = blockIdx.x * 256 + threadIdx.x;
    if (i < NUx) g_rp[y][i] += g_bsum[y][blockIdx.x];
    if (i == 0) g_rp[y][NUx] = NEx;
}

__global__ void k_fill(const int* __restrict__ suu, const int* __restrict__ duu,
                       const int* __restrict__ sui, const int* __restrict__ dui,
                       const int* __restrict__ siu, const int* __restrict__ diu) {
    int e = blockIdx.x * blockDim.x + threadIdx.x;
    if (e >= NEx) return;
    int y = blockIdx.y;
    const int* s; const int* d;
    if (y == 0)      { s = suu; d = duu; }
    else if (y == 1) { s = sui; d = dui; }
    else             { s = siu; d = diu; }
    int dn = d[e];
    int pos = g_rp[y][dn] + atomicAdd(&g_cur[y][dn], 1);
    g_col[y][pos] = s[e];
}

// ---------------- fused gather + GEMM (layer 0) ----------------

// Gather 4 nodes' mean-aggregated embeddings into sa rows r0..r0+3.
// 4 interleaved edge chains per warp for MLP. lane = float4 slice of the 128-d feature.
__device__ __forceinline__ void gather4(const float4* __restrict__ emb,
                                        const int* __restrict__ rp,
                                        const int* __restrict__ col,
                                        int n0, int lane,
                                        float (*sa)[D], float* smk, int r0) {
    int beg[4], end[4], deg[4];
    float4 acc[4];
#pragma unroll
    for (int j = 0; j < 4; j++) {
        beg[j] = __ldg(&rp[n0 + j]);
        end[j] = __ldg(&rp[n0 + j + 1]);
        deg[j] = end[j] - beg[j];
        acc[j] = make_float4(0.f, 0.f, 0.f, 0.f);
    }
    for (;;) {
        int c[4];
        bool act[4];
        bool any = false;
#pragma unroll
        for (int j = 0; j < 4; j++) {
            act[j] = beg[j] < end[j];
            c[j] = act[j] ? __ldg(&col[beg[j]]) : 0;
            any |= act[j];
        }
        if (!any) break;
#pragma unroll
        for (int j = 0; j < 4; j++) {
            if (act[j]) {
                float4 v = emb[(size_t)c[j] * 32 + lane];
                acc[j].x += v.x; acc[j].y += v.y; acc[j].z += v.z; acc[j].w += v.w;
                beg[j]++;
            }
        }
    }
#pragma unroll
    for (int j = 0; j < 4; j++) {
        float s = 1.0f / (float)max(deg[j], 1);
        float4 a = acc[j];
        a.x *= s; a.y *= s; a.z *= s; a.w *= s;
        *(float4*)&sa[r0 + j][lane * 4] = a;
        if (lane == 0) smk[r0 + j] = deg[j] > 0 ? 1.0f : 0.0f;
    }
}

// h_user = relu( mean_uu(eu)@W0 + b0*m0 + mean_iu(ei)@Wb + bb*m1 )
__global__ void __launch_bounds__(256) k_l0_user(
    const float* __restrict__ eu, const float* __restrict__ ei,
    const float* __restrict__ W0, const float* __restrict__ b0v,
    const float* __restrict__ Wb, const float* __restrict__ bbv,
    float* __restrict__ H) {
    __shared__ float sa0[32][D];
    __shared__ float sa1[32][D];
    __shared__ float smk0[32], smk1[32];
    const int tid  = threadIdx.x;
    const int base = blockIdx.x * 32;
    const int wid = tid >> 5, lane = tid & 31;

    int n0 = base + wid * 4;
    gather4((const float4*)eu, g_rp[0], g_col[0], n0, lane, sa0, smk0, wid * 4);
    gather4((const float4*)ei, g_rp[2], g_col[2], n0, lane, sa1, smk1, wid * 4);
    __syncthreads();

    const int jt = tid & 31, mt = tid >> 5;
    float4 bb0 = ((const float4*)b0v)[jt];
    float4 bb1 = ((const float4*)bbv)[jt];

    u64t acc[4][2];
#pragma unroll
    for (int i = 0; i < 4; i++) {
        float m0 = smk0[mt * 4 + i];
        float m1 = smk1[mt * 4 + i];
        acc[i][0] = pk2(bb0.x * m0 + bb1.x * m1, bb0.y * m0 + bb1.y * m1);
        acc[i][1] = pk2(bb0.z * m0 + bb1.z * m1, bb0.w * m0 + bb1.w * m1);
    }

    const float4* W0f = (const float4*)W0;
    const float4* Wbf = (const float4*)Wb;
#pragma unroll 4
    for (int k = 0; k < D; k++) {
        float4 w0 = W0f[k * 32 + jt];
        u64t w0a = pk2(w0.x, w0.y), w0b = pk2(w0.z, w0.w);
        float4 w1 = Wbf[k * 32 + jt];
        u64t w1a = pk2(w1.x, w1.y), w1b = pk2(w1.z, w1.w);
#pragma unroll
        for (int i = 0; i < 4; i++) {
            float a0 = sa0[mt * 4 + i][k];
            u64t a0p = pk2(a0, a0);
            fma2(acc[i][0], a0p, w0a);
            fma2(acc[i][1], a0p, w0b);
            float a1 = sa1[mt * 4 + i][k];
            u64t a1p = pk2(a1, a1);
            fma2(acc[i][0], a1p, w1a);
            fma2(acc[i][1], a1p, w1b);
        }
    }

#pragma unroll
    for (int i = 0; i < 4; i++) {
        float2 x = up2(acc[i][0]);
        float2 y = up2(acc[i][1]);
        float4 o = make_float4(fmaxf(x.x, 0.f), fmaxf(x.y, 0.f),
                               fmaxf(y.x, 0.f), fmaxf(y.y, 0.f));
        ((float4*)H)[(size_t)(base + mt * 4 + i) * 32 + jt] = o;
    }
}

// h_item = relu( mean_ui(eu)@W0 + b0*m0 )
__global__ void __launch_bounds__(256) k_l0_item(
    const float* __restrict__ eu,
    const float* __restrict__ W0, const float* __restrict__ b0v,
    float* __restrict__ H) {
    __shared__ float sa0[32][D];
    __shared__ float smk0[32];
    const int tid  = threadIdx.x;
    const int base = blockIdx.x * 32;
    const int wid = tid >> 5, lane = tid & 31;

    gather4((const float4*)eu, g_rp[1], g_col[1], base + wid * 4, lane, sa0, smk0, wid * 4);
    __syncthreads();

    const int jt = tid & 31, mt = tid >> 5;
    float4 bb0 = ((const float4*)b0v)[jt];

    u64t acc[4][2];
#pragma unroll
    for (int i = 0; i < 4; i++) {
        float m0 = smk0[mt * 4 + i];
        acc[i][0] = pk2(bb0.x * m0, bb0.y * m0);
        acc[i][1] = pk2(bb0.z * m0, bb0.w * m0);
    }

    const float4* W0f = (const float4*)W0;
#pragma unroll 4
    for (int k = 0; k < D; k++) {
        float4 w0 = W0f[k * 32 + jt];
        u64t w0a = pk2(w0.x, w0.y), w0b = pk2(w0.z, w0.w);
#pragma unroll
        for (int i = 0; i < 4; i++) {
            float a0 = sa0[mt * 4 + i][k];
            u64t a0p = pk2(a0, a0);
            fma2(acc[i][0], a0p, w0a);
            fma2(acc[i][1], a0p, w0b);
        }
    }

#pragma unroll
    for (int i = 0; i < 4; i++) {
        float2 x = up2(acc[i][0]);
        float2 y = up2(acc[i][1]);
        float4 o = make_float4(fmaxf(x.x, 0.f), fmaxf(x.y, 0.f),
                               fmaxf(y.x, 0.f), fmaxf(y.y, 0.f));
        ((float4*)H)[(size_t)(base + mt * 4 + i) * 32 + jt] = o;
    }
}

// ---------------- layer 1 ----------------

// P[N,16] = H[N,128] @ W1[128,16] + b1. 64 nodes/block.
__global__ void __launch_bounds__(256) k_proj(const float* __restrict__ Hm,
                                              const float* __restrict__ W1,
                                              const float* __restrict__ b1,
                                              float* __restrict__ P, int N) {
    __shared__ float sh[64][132];
    __shared__ float sw[D * DO];
    int tid  = threadIdx.x;
    int base = blockIdx.x * 64;
#pragma unroll
    for (int i = 0; i < 2; i++) {
        int f = tid + i * 256;
        ((float4*)sw)[f] = ((const float4*)W1)[f];
    }
#pragma unroll
    for (int i = 0; i < 8; i++) {
        int f = tid + i * 256;
        int r = f >> 5, c = f & 31;
        int n = base + r; if (n >= N) n = N - 1;
        float4 v = ((const float4*)Hm)[(size_t)n * 32 + c];
        *(float4*)&sh[r][c * 4] = v;
    }
    __syncthreads();
    int m = tid >> 2, q = tid & 3;
    float4 bb = ((const float4*)b1)[q];
    float a0 = bb.x, a1 = bb.y, a2 = bb.z, a3 = bb.w;
#pragma unroll 8
    for (int k = 0; k < D; k++) {
        float hk = sh[m][k];
        float4 w = ((float4*)sw)[k * 4 + q];
        a0 += hk * w.x; a1 += hk * w.y; a2 += hk * w.z; a3 += hk * w.w;
    }
    int n = base + m;
    if (n < N) ((float4*)P)[n * 4 + q] = make_float4(a0, a1, a2, a3);
}

// out[n] = mean_uu(p_user) + mean_iu(p_item), gathered directly into d_out.
__global__ void k_l1(float* __restrict__ out) {
    int t = blockIdx.x * blockDim.x + threadIdx.x;
    if (t >= NUx * 4) return;
    int n = t >> 2, lane = t & 3;
    int b0 = g_rp[0][n], e0 = g_rp[0][n + 1];
    int b2 = g_rp[2][n], e2 = g_rp[2][n + 1];
    float4 a = make_float4(0.f, 0.f, 0.f, 0.f);
    float4 c = make_float4(0.f, 0.f, 0.f, 0.f);
    int eA = b0, eB = b2;
    while (eA < e0 && eB < e2) {
        int s0 = g_col[0][eA], s2 = g_col[2][eB];
        float4 v0 = ((const float4*)g_p_user)[(size_t)s0 * 4 + lane];
        float4 v2 = ((const float4*)g_p_item)[(size_t)s2 * 4 + lane];
        a.x += v0.x; a.y += v0.y; a.z += v0.z; a.w += v0.w;
        c.x += v2.x; c.y += v2.y; c.z += v2.z; c.w += v2.w;
        eA++; eB++;
    }
    for (; eA < e0; eA++) {
        int s0 = g_col[0][eA];
        float4 v0 = ((const float4*)g_p_user)[(size_t)s0 * 4 + lane];
        a.x += v0.x; a.y += v0.y; a.z += v0.z; a.w += v0.w;
    }
    for (; eB < e2; eB++) {
        int s2 = g_col[2][eB];
        float4 v2 = ((const float4*)g_p_item)[(size_t)s2 * 4 + lane];
        c.x += v2.x; c.y += v2.y; c.z += v2.z; c.w += v2.w;
    }
    float i0 = 1.0f / (float)max(e0 - b0, 1);
    float i2 = 1.0f / (float)max(e2 - b2, 1);
    ((float4*)out)[t] = make_float4(a.x * i0 + c.x * i2, a.y * i0 + c.y * i2,
                                    a.z * i0 + c.z * i2, a.w * i0 + c.w * i2);
}

// ---------------- launch ----------------
extern "C" void kernel_launch(void* const* d_in, const int* in_sizes, int n_in,
                              void* d_out, int out_size) {
    const float* embed_user = (const float*)d_in[0];
    const float* embed_item = (const float*)d_in[1];
    const int* src_uu = (const int*)d_in[2];
    const int* dst_uu = (const int*)d_in[3];
    const int* src_ui = (const int*)d_in[4];
    const int* dst_ui = (const int*)d_in[5];
    const int* src_iu = (const int*)d_in[6];
    const int* dst_iu = (const int*)d_in[7];
    const float* W0_uu = (const float*)d_in[8];
    const float* b0_uu = (const float*)d_in[9];
    const float* W0_ui = (const float*)d_in[10];
    const float* b0_ui = (const float*)d_in[11];
    const float* W0_iu = (const float*)d_in[12];
    const float* b0_iu = (const float*)d_in[13];
    const float* W1_uu = (const float*)d_in[14];
    const float* b1_uu = (const float*)d_in[15];
    const float* W1_iu = (const float*)d_in[18];
    const float* b1_iu = (const float*)d_in[19];

    float *h_user, *h_item, *p_user, *p_item;
    cudaGetSymbolAddress((void**)&h_user, g_h_user);
    cudaGetSymbolAddress((void**)&h_item, g_h_item);
    cudaGetSymbolAddress((void**)&p_user, g_p_user);
    cudaGetSymbolAddress((void**)&p_item, g_p_item);

    // CSR build (3 etypes)
    k_zero_small<<<NB, 256>>>();
    k_degree<<<EB, 256>>>(dst_uu, dst_ui, dst_iu);
    k_scan1<<<dim3(NB, 3), 256>>>();
    k_scan2<<<3, 512>>>();
    k_scan3<<<dim3(NB, 3), 256>>>();
    k_fill<<<dim3(EB, 3), 256>>>(src_uu, dst_uu, src_ui, dst_ui, src_iu, dst_iu);

    // Layer 0: fused gather-mean + dual/single GEMM + relu
    k_l0_user<<<NUx / 32, 256>>>(embed_user, embed_item,
                                 W0_uu, b0_uu, W0_iu, b0_iu, h_user);
    k_l0_item<<<NIx / 32, 256>>>(embed_user, W0_ui, b0_ui, h_item);

    // Layer 1: project to 16-d, then gather-mean-combine into d_out
    k_proj<<<(NUx + 63) / 64, 256>>>(h_user, W1_uu, b1_uu, p_user, NUx);
    k_proj<<<(NIx + 63) / 64, 256>>>(h_item, W1_iu, b1_iu, p_item, NIx);
    k_l1<<<(NUx * 4 + 255) / 256, 256>>>((float*)d_out);
}

// round 4
// speedup vs baseline: 1.7031x; 1.4434x over previous
#include <cuda_runtime.h>
#include <cuda_bf16.h>
#include <cstdint>

#define NUx 100000
#define NIx 100000
#define NP  100096          // padded to multiple of 128
#define NEx 600000
#define D   128
#define DO  16
#define NB  391             // ceil(100000/256)
#define EB  2344            // ceil(600000/256)

// etype ids: 0 = uu (dst user, src user), 1 = ui (dst item, src user), 2 = iu (dst user, src item)
__device__ int g_deg[3][NP];        // padded entries stay 0 (never written)
__device__ int g_cur[3][NUx];
__device__ int g_rp[3][NUx + 1];
__device__ int g_col[3][NEx];
__device__ int g_bsum[3][512];
__device__ __nv_bfloat16 g_Ah[3][NP * D];   // hi bf16 of mean-agg
__device__ __nv_bfloat16 g_Al[3][NP * D];   // lo bf16 residual
__device__ __nv_bfloat16 g_Wt[3][2][D * D]; // [et 0:uu 1:iu 2:ui][0:hi 1:lo][n*128+k]
__device__ float g_h_user[NP * D];
__device__ float g_h_item[NP * D];
__device__ float g_p_user[NUx * DO];
__device__ float g_p_item[NIx * DO];

// ---------------- helpers ----------------
__device__ __forceinline__ uint32_t smem_u32(const void* p) {
    uint32_t a;
    asm("{ .reg .u64 t; cvta.to.shared.u64 t, %1; cvt.u32.u64 %0, t; }" : "=r"(a) : "l"(p));
    return a;
}
__device__ __forceinline__ void cpa16(uint32_t dst, const void* src) {
    asm volatile("cp.async.ca.shared.global [%0], [%1], 16;" :: "r"(dst), "l"(src));
}
#define CPA_COMMIT() asm volatile("cp.async.commit_group;" ::: "memory")
#define CPA_WAIT1()  asm volatile("cp.async.wait_group 1;" ::: "memory")
#define CPA_WAIT0()  asm volatile("cp.async.wait_group 0;" ::: "memory")

__device__ __forceinline__ void mma16816(float* c, const uint32_t* a, uint32_t b0, uint32_t b1) {
    asm volatile(
        "mma.sync.aligned.m16n8k16.row.col.f32.bf16.bf16.f32 "
        "{%0,%1,%2,%3}, {%4,%5,%6,%7}, {%8,%9}, {%0,%1,%2,%3};"
        : "+f"(c[0]), "+f"(c[1]), "+f"(c[2]), "+f"(c[3])
        : "r"(a[0]), "r"(a[1]), "r"(a[2]), "r"(a[3]), "r"(b0), "r"(b1));
}
__device__ __forceinline__ void hilo(float v, unsigned short& h, unsigned short& l) {
    __nv_bfloat16 hb = __float2bfloat16(v);
    __nv_bfloat16 lb = __float2bfloat16(v - __bfloat162float(hb));
    h = __bfloat16_as_ushort(hb);
    l = __bfloat16_as_ushort(lb);
}

// ---------------- CSR build ----------------
__global__ void k_zero_small() {
    int i = blockIdx.x * blockDim.x + threadIdx.x;
    if (i < NUx) {
#pragma unroll
        for (int y = 0; y < 3; y++) { g_deg[y][i] = 0; g_cur[y][i] = 0; }
    }
}
__global__ void k_degree(const int* __restrict__ duu, const int* __restrict__ dui,
                         const int* __restrict__ diu) {
    int e = blockIdx.x * blockDim.x + threadIdx.x;
    if (e < NEx) {
        atomicAdd(&g_deg[0][duu[e]], 1);
        atomicAdd(&g_deg[1][dui[e]], 1);
        atomicAdd(&g_deg[2][diu[e]], 1);
    }
}
__global__ void k_scan1() {
    __shared__ int s[256];
    int y = blockIdx.y, t = threadIdx.x;
    int i = blockIdx.x * 256 + t;
    int v = (i < NUx) ? g_deg[y][i] : 0;
    s[t] = v;
    __syncthreads();
#pragma unroll
    for (int off = 1; off < 256; off <<= 1) {
        int x = (t >= off) ? s[t - off] : 0;
        __syncthreads();
        s[t] += x;
        __syncthreads();
    }
    if (i < NUx) g_rp[y][i] = s[t] - v;
    if (t == 255) g_bsum[y][blockIdx.x] = s[255];
}
__global__ void k_scan2() {
    __shared__ int s[512];
    int y = blockIdx.x, t = threadIdx.x;
    int v = (t < NB) ? g_bsum[y][t] : 0;
    s[t] = v;
    __syncthreads();
#pragma unroll
    for (int off = 1; off < 512; off <<= 1) {
        int x = (t >= off) ? s[t - off] : 0;
        __syncthreads();
        s[t] += x;
        __syncthreads();
    }
    if (t < NB) g_bsum[y][t] = s[t] - v;
}
__global__ void k_scan3() {
    int y = blockIdx.y;
    int i = blockIdx.x * 256 + threadIdx.x;
    if (i < NUx) g_rp[y][i] += g_bsum[y][blockIdx.x];
    if (i == 0) g_rp[y][NUx] = NEx;
}
__global__ void k_fill(const int* __restrict__ suu, const int* __restrict__ duu,
                       const int* __restrict__ sui, const int* __restrict__ dui,
                       const int* __restrict__ siu, const int* __restrict__ diu) {
    int e = blockIdx.x * blockDim.x + threadIdx.x;
    if (e >= NEx) return;
    int y = blockIdx.y;
    const int* s; const int* d;
    if (y == 0)      { s = suu; d = duu; }
    else if (y == 1) { s = sui; d = dui; }
    else             { s = siu; d = diu; }
    int dn = d[e];
    int pos = g_rp[y][dn] + atomicAdd(&g_cur[y][dn], 1);
    g_col[y][pos] = s[e];
}

// ---------------- weight conversion: W[k][n] f32 -> Wt[n][k] bf16 hi/lo ----------------
__global__ void k_wcvt(const float* __restrict__ Wuu, const float* __restrict__ Wiu,
                       const float* __restrict__ Wui) {
    int et = blockIdx.y;            // 0:uu 1:iu 2:ui
    int k = blockIdx.x;             // 0..127
    int n = threadIdx.x;            // 0..127
    const float* W = (et == 0) ? Wuu : (et == 1) ? Wiu : Wui;
    float v = W[k * 128 + n];
    unsigned short h, l;
    hilo(v, h, l);
    g_Wt[et][0][n * 128 + k] = __ushort_as_bfloat16(h);
    g_Wt[et][1][n * 128 + k] = __ushort_as_bfloat16(l);
}

// ---------------- aggregation: warp per node, mean -> bf16 hi/lo ----------------
__global__ void __launch_bounds__(256) k_agg(const float4* __restrict__ eu,
                                             const float4* __restrict__ ei) {
    int wid = threadIdx.x >> 5, lane = threadIdx.x & 31;
    int node = blockIdx.x * 8 + wid;
    if (node >= NP) return;
    int et = blockIdx.y;
    float4 acc = make_float4(0.f, 0.f, 0.f, 0.f);
    if (node < NUx) {
        const int* rp  = g_rp[et];
        const int* col = g_col[et];
        const float4* emb = (et == 2) ? ei : eu;
        int b = __ldg(&rp[node]), e = __ldg(&rp[node + 1]);
        int i = b;
        for (; i + 4 <= e; i += 4) {
            int c0 = __ldg(&col[i]),     c1 = __ldg(&col[i + 1]);
            int c2 = __ldg(&col[i + 2]), c3 = __ldg(&col[i + 3]);
            float4 v0 = emb[(size_t)c0 * 32 + lane];
            float4 v1 = emb[(size_t)c1 * 32 + lane];
            float4 v2 = emb[(size_t)c2 * 32 + lane];
            float4 v3 = emb[(size_t)c3 * 32 + lane];
            acc.x += (v0.x + v1.x) + (v2.x + v3.x);
            acc.y += (v0.y + v1.y) + (v2.y + v3.y);
            acc.z += (v0.z + v1.z) + (v2.z + v3.z);
            acc.w += (v0.w + v1.w) + (v2.w + v3.w);
        }
        for (; i < e; i++) {
            int c = __ldg(&col[i]);
            float4 v = emb[(size_t)c * 32 + lane];
            acc.x += v.x; acc.y += v.y; acc.z += v.z; acc.w += v.w;
        }
        float s = 1.0f / (float)max(e - b, 1);
        acc.x *= s; acc.y *= s; acc.z *= s; acc.w *= s;
    }
    unsigned short h0, l0, h1, l1, h2, l2, h3, l3;
    hilo(acc.x, h0, l0); hilo(acc.y, h1, l1); hilo(acc.z, h2, l2); hilo(acc.w, h3, l3);
    uint2 hv = make_uint2((uint32_t)h0 | ((uint32_t)h1 << 16),
                          (uint32_t)h2 | ((uint32_t)h3 << 16));
    uint2 lv = make_uint2((uint32_t)l0 | ((uint32_t)l1 << 16),
                          (uint32_t)l2 | ((uint32_t)l3 << 16));
    ((uint2*)g_Ah[et])[(size_t)node * 32 + lane] = hv;
    ((uint2*)g_Al[et])[(size_t)node * 32 + lane] = lv;
}

// ---------------- layer-0 GEMM on HMMA (mma.sync bf16, 3-term split) ----------------
// C[128x128] = sum over NSEG segments A_s[128xK128] @ B_s[K128x128]; epilogue bias+mask+relu.
struct SegP {
    const __nv_bfloat16* A[6];
    const __nv_bfloat16* B[6];
    const float* b0; const float* b1;
    const int* dg0;  const int* dg1;
    float* H;
};

template <int NSEG>
__global__ void __launch_bounds__(256, 2) k_hgemm(SegP sp) {
    extern __shared__ char S[];
    const int tid  = threadIdx.x;
    const int wid  = tid >> 5, lane = tid & 31;
    const int gId  = lane >> 2, t2 = (lane & 3) * 2;
    const int mrow = (wid & 3) * 32, ncol = (wid >> 2) * 64;
    const int mbase = blockIdx.x * 128;
    const uint32_t sb = smem_u32(S);

    __shared__ const __nv_bfloat16* tA[6];
    __shared__ const __nv_bfloat16* tB[6];
    if (tid < NSEG) { tA[tid] = sp.A[tid]; tB[tid] = sp.B[tid]; }
    __syncthreads();

    float acc[2][8][4];
#pragma unroll
    for (int mi = 0; mi < 2; mi++)
#pragma unroll
        for (int ni = 0; ni < 8; ni++)
#pragma unroll
            for (int q = 0; q < 4; q++) acc[mi][ni][q] = 0.f;

    const int NC = NSEG * 4;

    auto load_chunk = [&](int buf, int c) {
        int seg = c >> 2, kc = c & 3;
        const __nv_bfloat16* Ap = tA[seg];
        const __nv_bfloat16* Bp = tB[seg];
#pragma unroll
        for (int i = 0; i < 2; i++) {
            int idx = tid + i * 256;              // 0..511
            int r = idx >> 2, s4 = idx & 3;
            cpa16(sb + buf * 10240 + r * 80 + s4 * 16,
                  Ap + (size_t)(mbase + r) * 128 + kc * 32 + s4 * 8);
            cpa16(sb + 20480 + buf * 10240 + r * 80 + s4 * 16,
                  Bp + (size_t)r * 128 + kc * 32 + s4 * 8);
        }
    };

    load_chunk(0, 0);
    CPA_COMMIT();
    for (int c = 0; c < NC; c++) {
        if (c + 1 < NC) { load_chunk((c + 1) & 1, c + 1); CPA_COMMIT(); CPA_WAIT1(); }
        else            { CPA_WAIT0(); }
        __syncthreads();
        const char* sAb = S + (c & 1) * 10240;
        const char* sBb = S + 20480 + (c & 1) * 10240;
#pragma unroll
        for (int ks = 0; ks < 2; ks++) {
            const int kb = ks * 16;
            uint32_t a[2][4];
#pragma unroll
            for (int mi = 0; mi < 2; mi++) {
                const char* p = sAb + ((mrow + mi * 16 + gId) * 40 + kb + t2) * 2;
                a[mi][0] = *(const uint32_t*)(p);
                a[mi][1] = *(const uint32_t*)(p + 640);    // +8 rows
                a[mi][2] = *(const uint32_t*)(p + 16);     // +8 k
                a[mi][3] = *(const uint32_t*)(p + 656);
            }
#pragma unroll
            for (int ni = 0; ni < 8; ni++) {
                const char* q = sBb + ((ncol + ni * 8 + gId) * 40 + kb + t2) * 2;
                uint32_t b0 = *(const uint32_t*)(q);
                uint32_t b1 = *(const uint32_t*)(q + 16);
                mma16816(acc[0][ni], a[0], b0, b1);
                mma16816(acc[1][ni], a[1], b0, b1);
            }
        }
        __syncthreads();
    }

    // epilogue: stage C in SMEM, then masked bias + relu + coalesced store
    float* stg = (float*)S;
#pragma unroll
    for (int mi = 0; mi < 2; mi++)
#pragma unroll
        for (int ni = 0; ni < 8; ni++) {
            int r0 = mrow + mi * 16 + gId, c0 = ncol + ni * 8 + t2;
            *(float2*)&stg[r0 * 132 + c0]       = make_float2(acc[mi][ni][0], acc[mi][ni][1]);
            *(float2*)&stg[(r0 + 8) * 132 + c0] = make_float2(acc[mi][ni][2], acc[mi][ni][3]);
        }
    __syncthreads();
#pragma unroll
    for (int j = 0; j < 16; j++) {
        int idx = tid + j * 256;                  // 4096 float4s
        int r = idx >> 5, c4 = idx & 31;
        int gr = mbase + r;
        float4 v = *(float4*)&stg[r * 132 + c4 * 4];
        float m0 = (__ldg(&sp.dg0[gr]) > 0) ? 1.f : 0.f;
        float4 bb = __ldg(&((const float4*)sp.b0)[c4]);
        v.x += m0 * bb.x; v.y += m0 * bb.y; v.z += m0 * bb.z; v.w += m0 * bb.w;
        if (NSEG == 6) {
            float m1 = (__ldg(&sp.dg1[gr]) > 0) ? 1.f : 0.f;
            float4 b2 = __ldg(&((const float4*)sp.b1)[c4]);
            v.x += m1 * b2.x; v.y += m1 * b2.y; v.z += m1 * b2.z; v.w += m1 * b2.w;
        }
        v.x = fmaxf(v.x, 0.f); v.y = fmaxf(v.y, 0.f);
        v.z = fmaxf(v.z, 0.f); v.w = fmaxf(v.w, 0.f);
        ((float4*)sp.H)[(size_t)gr * 32 + c4] = v;
    }
}

// ---------------- layer 1 ----------------
__global__ void __launch_bounds__(256) k_proj(const float* __restrict__ Hm,
                                              const float* __restrict__ W1,
                                              const float* __restrict__ b1,
                                              float* __restrict__ P, int N) {
    __shared__ float sh[64][132];
    __shared__ float sw[D * DO];
    int tid  = threadIdx.x;
    int base = blockIdx.x * 64;
#pragma unroll
    for (int i = 0; i < 2; i++) {
        int f = tid + i * 256;
        ((float4*)sw)[f] = ((const float4*)W1)[f];
    }
#pragma unroll
    for (int i = 0; i < 8; i++) {
        int f = tid + i * 256;
        int r = f >> 5, c = f & 31;
        int n = base + r; if (n >= N) n = N - 1;
        float4 v = ((const float4*)Hm)[(size_t)n * 32 + c];
        *(float4*)&sh[r][c * 4] = v;
    }
    __syncthreads();
    int m = tid >> 2, q = tid & 3;
    float4 bb = ((const float4*)b1)[q];
    float a0 = bb.x, a1 = bb.y, a2 = bb.z, a3 = bb.w;
#pragma unroll 8
    for (int k = 0; k < D; k++) {
        float hk = sh[m][k];
        float4 w = ((float4*)sw)[k * 4 + q];
        a0 += hk * w.x; a1 += hk * w.y; a2 += hk * w.z; a3 += hk * w.w;
    }
    int n = base + m;
    if (n < N) ((float4*)P)[n * 4 + q] = make_float4(a0, a1, a2, a3);
}

__global__ void k_l1(float* __restrict__ out) {
    int t = blockIdx.x * blockDim.x + threadIdx.x;
    if (t >= NUx * 4) return;
    int n = t >> 2, lane = t & 3;
    int b0 = g_rp[0][n], e0 = g_rp[0][n + 1];
    int b2 = g_rp[2][n], e2 = g_rp[2][n + 1];
    float4 a = make_float4(0.f, 0.f, 0.f, 0.f);
    float4 c = make_float4(0.f, 0.f, 0.f, 0.f);
    int eA = b0, eB = b2;
    while (eA < e0 && eB < e2) {
        int s0 = g_col[0][eA], s2 = g_col[2][eB];
        float4 v0 = ((const float4*)g_p_user)[(size_t)s0 * 4 + lane];
        float4 v2 = ((const float4*)g_p_item)[(size_t)s2 * 4 + lane];
        a.x += v0.x; a.y += v0.y; a.z += v0.z; a.w += v0.w;
        c.x += v2.x; c.y += v2.y; c.z += v2.z; c.w += v2.w;
        eA++; eB++;
    }
    for (; eA < e0; eA++) {
        int s0 = g_col[0][eA];
        float4 v0 = ((const float4*)g_p_user)[(size_t)s0 * 4 + lane];
        a.x += v0.x; a.y += v0.y; a.z += v0.z; a.w += v0.w;
    }
    for (; eB < e2; eB++) {
        int s2 = g_col[2][eB];
        float4 v2 = ((const float4*)g_p_item)[(size_t)s2 * 4 + lane];
        c.x += v2.x; c.y += v2.y; c.z += v2.z; c.w += v2.w;
    }
    float i0 = 1.0f / (float)max(e0 - b0, 1);
    float i2 = 1.0f / (float)max(e2 - b2, 1);
    ((float4*)out)[t] = make_float4(a.x * i0 + c.x * i2, a.y * i0 + c.y * i2,
                                    a.z * i0 + c.z * i2, a.w * i0 + c.w * i2);
}

// ---------------- launch ----------------
extern "C" void kernel_launch(void* const* d_in, const int* in_sizes, int n_in,
                              void* d_out, int out_size) {
    const float* embed_user = (const float*)d_in[0];
    const float* embed_item = (const float*)d_in[1];
    const int* src_uu = (const int*)d_in[2];
    const int* dst_uu = (const int*)d_in[3];
    const int* src_ui = (const int*)d_in[4];
    const int* dst_ui = (const int*)d_in[5];
    const int* src_iu = (const int*)d_in[6];
    const int* dst_iu = (const int*)d_in[7];
    const float* W0_uu = (const float*)d_in[8];
    const float* b0_uu = (const float*)d_in[9];
    const float* W0_ui = (const float*)d_in[10];
    const float* b0_ui = (const float*)d_in[11];
    const float* W0_iu = (const float*)d_in[12];
    const float* b0_iu = (const float*)d_in[13];
    const float* W1_uu = (const float*)d_in[14];
    const float* b1_uu = (const float*)d_in[15];
    const float* W1_iu = (const float*)d_in[18];
    const float* b1_iu = (const float*)d_in[19];

    float *h_user, *h_item, *p_user, *p_item;
    int* degs;
    __nv_bfloat16 *ah, *al, *wt;
    cudaGetSymbolAddress((void**)&h_user, g_h_user);
    cudaGetSymbolAddress((void**)&h_item, g_h_item);
    cudaGetSymbolAddress((void**)&p_user, g_p_user);
    cudaGetSymbolAddress((void**)&p_item, g_p_item);
    cudaGetSymbolAddress((void**)&degs, g_deg);
    cudaGetSymbolAddress((void**)&ah, g_Ah);
    cudaGetSymbolAddress((void**)&al, g_Al);
    cudaGetSymbolAddress((void**)&wt, g_Wt);

    const __nv_bfloat16* Ah0 = ah;                      // uu (dst user)
    const __nv_bfloat16* Ah1 = ah + (size_t)NP * D;     // ui (dst item)
    const __nv_bfloat16* Ah2 = ah + (size_t)2 * NP * D; // iu (dst user)
    const __nv_bfloat16* Al0 = al;
    const __nv_bfloat16* Al1 = al + (size_t)NP * D;
    const __nv_bfloat16* Al2 = al + (size_t)2 * NP * D;
    const __nv_bfloat16* WhUU = wt;                 // g_Wt[0][0]
    const __nv_bfloat16* WlUU = wt + 16384;         // g_Wt[0][1]
    const __nv_bfloat16* WhIU = wt + 2 * 16384;     // g_Wt[1][0]
    const __nv_bfloat16* WlIU = wt + 3 * 16384;
    const __nv_bfloat16* WhUI = wt + 4 * 16384;     // g_Wt[2][0]
    const __nv_bfloat16* WlUI = wt + 5 * 16384;

    const int SMEM_G = 128 * 132 * 4;   // 67584, covers pipeline buffers (40960) too
    cudaFuncSetAttribute(k_hgemm<6>, cudaFuncAttributeMaxDynamicSharedMemorySize, SMEM_G);
    cudaFuncSetAttribute(k_hgemm<3>, cudaFuncAttributeMaxDynamicSharedMemorySize, SMEM_G);

    // CSR build
    k_zero_small<<<NB, 256>>>();
    k_degree<<<EB, 256>>>(dst_uu, dst_ui, dst_iu);
    k_scan1<<<dim3(NB, 3), 256>>>();
    k_scan2<<<3, 512>>>();
    k_scan3<<<dim3(NB, 3), 256>>>();
    k_fill<<<dim3(EB, 3), 256>>>(src_uu, dst_uu, src_ui, dst_ui, src_iu, dst_iu);

    // weight conversion + aggregation (f32 mean -> bf16 hi/lo)
    k_wcvt<<<dim3(128, 3), 128>>>(W0_uu, W0_iu, W0_ui);
    k_agg<<<dim3((NP + 7) / 8, 3), 256>>>((const float4*)embed_user,
                                          (const float4*)embed_item);

    // layer-0 GEMMs on HMMA
    SegP su;
    su.A[0] = Ah0; su.A[1] = Al0; su.A[2] = Ah0; su.A[3] = Ah2; su.A[4] = Al2; su.A[5] = Ah2;
    su.B[0] = WhUU; su.B[1] = WhUU; su.B[2] = WlUU; su.B[3] = WhIU; su.B[4] = WhIU; su.B[5] = WlIU;
    su.b0 = b0_uu; su.b1 = b0_iu;
    su.dg0 = degs; su.dg1 = degs + 2 * NP;
    su.H = h_user;
    k_hgemm<6><<<NP / 128, 256, SMEM_G>>>(su);

    SegP si;
    si.A[0] = Ah1; si.A[1] = Al1; si.A[2] = Ah1;
    si.A[3] = Ah1; si.A[4] = Al1; si.A[5] = Ah1;
    si.B[0] = WhUI; si.B[1] = WhUI; si.B[2] = WlUI;
    si.B[3] = WhUI; si.B[4] = WhUI; si.B[5] = WlUI;
    si.b0 = b0_ui; si.b1 = b0_ui;
    si.dg0 = degs + NP; si.dg1 = degs + NP;
    si.H = h_item;
    k_hgemm<3><<<NP / 128, 256, SMEM_G>>>(si);

    // layer 1
    k_proj<<<(NUx + 63) / 64, 256>>>(h_user, W1_uu, b1_uu, p_user, NUx);
    k_proj<<<(NIx + 63) / 64, 256>>>(h_item, W1_iu, b1_iu, p_item, NIx);
    k_l1<<<(NUx * 4 + 255) / 256, 256>>>((float*)d_out);
}

// round 5
// speedup vs baseline: 2.1556x; 1.2657x over previous
#include <cuda_runtime.h>
#include <cuda_bf16.h>
#include <cstdint>

#define NUx 100000
#define NIx 100000
#define NP  100096          // padded to multiple of 128
#define NEx 600000
#define D   128
#define DO  16
#define NB  391             // ceil(100000/256)
#define EB  2344            // ceil(600000/256)

// etype ids: 0 = uu (dst user, src user), 1 = ui (dst item, src user), 2 = iu (dst user, src item)
__device__ int g_deg[3][NP];        // padded entries stay 0 (never written)
__device__ int g_cur[3][NUx];
__device__ int g_rp[3][NUx + 1];
__device__ int g_col[3][NEx];
__device__ int g_bsum[3][512];
__device__ __nv_bfloat16 g_Ah[3][NP * D];   // hi bf16 of mean-agg
__device__ __nv_bfloat16 g_Al[3][NP * D];   // lo bf16 residual
__device__ __nv_bfloat16 g_Wt[3][2][D * D]; // [et 0:uu 1:iu 2:ui][0:hi 1:lo][n*128+k]
__device__ float g_p_user[NUx * DO];
__device__ float g_p_item[NIx * DO];

// ---------------- helpers ----------------
__device__ __forceinline__ uint32_t smem_u32(const void* p) {
    uint32_t a;
    asm("{ .reg .u64 t; cvta.to.shared.u64 t, %1; cvt.u32.u64 %0, t; }" : "=r"(a) : "l"(p));
    return a;
}
__device__ __forceinline__ void cpa16(uint32_t dst, const void* src) {
    asm volatile("cp.async.ca.shared.global [%0], [%1], 16;" :: "r"(dst), "l"(src));
}
#define CPA_COMMIT() asm volatile("cp.async.commit_group;" ::: "memory")
#define CPA_WAIT1()  asm volatile("cp.async.wait_group 1;" ::: "memory")
#define CPA_WAIT0()  asm volatile("cp.async.wait_group 0;" ::: "memory")

__device__ __forceinline__ void mma16816(float* c, const uint32_t* a, uint32_t b0, uint32_t b1) {
    asm volatile(
        "mma.sync.aligned.m16n8k16.row.col.f32.bf16.bf16.f32 "
        "{%0,%1,%2,%3}, {%4,%5,%6,%7}, {%8,%9}, {%0,%1,%2,%3};"
        : "+f"(c[0]), "+f"(c[1]), "+f"(c[2]), "+f"(c[3])
        : "r"(a[0]), "r"(a[1]), "r"(a[2]), "r"(a[3]), "r"(b0), "r"(b1));
}
__device__ __forceinline__ void hilo(float v, unsigned short& h, unsigned short& l) {
    __nv_bfloat16 hb = __float2bfloat16(v);
    __nv_bfloat16 lb = __float2bfloat16(v - __bfloat162float(hb));
    h = __bfloat16_as_ushort(hb);
    l = __bfloat16_as_ushort(lb);
}

// ---------------- CSR build ----------------
__global__ void k_zero_small() {
    int i = blockIdx.x * blockDim.x + threadIdx.x;
    if (i < NUx) {
#pragma unroll
        for (int y = 0; y < 3; y++) { g_deg[y][i] = 0; g_cur[y][i] = 0; }
    }
}
__global__ void k_degree(const int* __restrict__ duu, const int* __restrict__ dui,
                         const int* __restrict__ diu) {
    int e = blockIdx.x * blockDim.x + threadIdx.x;
    if (e < NEx) {
        atomicAdd(&g_deg[0][duu[e]], 1);
        atomicAdd(&g_deg[1][dui[e]], 1);
        atomicAdd(&g_deg[2][diu[e]], 1);
    }
}
__global__ void k_scan1() {
    __shared__ int s[256];
    int y = blockIdx.y, t = threadIdx.x;
    int i = blockIdx.x * 256 + t;
    int v = (i < NUx) ? g_deg[y][i] : 0;
    s[t] = v;
    __syncthreads();
#pragma unroll
    for (int off = 1; off < 256; off <<= 1) {
        int x = (t >= off) ? s[t - off] : 0;
        __syncthreads();
        s[t] += x;
        __syncthreads();
    }
    if (i < NUx) g_rp[y][i] = s[t] - v;
    if (t == 255) g_bsum[y][blockIdx.x] = s[255];
}
__global__ void k_scan2() {
    __shared__ int s[512];
    int y = blockIdx.x, t = threadIdx.x;
    int v = (t < NB) ? g_bsum[y][t] : 0;
    s[t] = v;
    __syncthreads();
#pragma unroll
    for (int off = 1; off < 512; off <<= 1) {
        int x = (t >= off) ? s[t - off] : 0;
        __syncthreads();
        s[t] += x;
        __syncthreads();
    }
    if (t < NB) g_bsum[y][t] = s[t] - v;
}
__global__ void k_scan3() {
    int y = blockIdx.y;
    int i = blockIdx.x * 256 + threadIdx.x;
    if (i < NUx) g_rp[y][i] += g_bsum[y][blockIdx.x];
    if (i == 0) g_rp[y][NUx] = NEx;
}
__global__ void k_fill(const int* __restrict__ suu, const int* __restrict__ duu,
                       const int* __restrict__ sui, const int* __restrict__ dui,
                       const int* __restrict__ siu, const int* __restrict__ diu) {
    int e = blockIdx.x * blockDim.x + threadIdx.x;
    if (e >= NEx) return;
    int y = blockIdx.y;
    const int* s; const int* d;
    if (y == 0)      { s = suu; d = duu; }
    else if (y == 1) { s = sui; d = dui; }
    else             { s = siu; d = diu; }
    int dn = d[e];
    int pos = g_rp[y][dn] + atomicAdd(&g_cur[y][dn], 1);
    g_col[y][pos] = s[e];
}

// ---------------- weight conversion: W[k][n] f32 -> Wt[n][k] bf16 hi/lo ----------------
__global__ void k_wcvt(const float* __restrict__ Wuu, const float* __restrict__ Wiu,
                       const float* __restrict__ Wui) {
    int et = blockIdx.y;            // 0:uu 1:iu 2:ui
    int k = blockIdx.x;             // 0..127
    int n = threadIdx.x;            // 0..127
    const float* W = (et == 0) ? Wuu : (et == 1) ? Wiu : Wui;
    float v = W[k * 128 + n];
    unsigned short h, l;
    hilo(v, h, l);
    g_Wt[et][0][n * 128 + k] = __ushort_as_bfloat16(h);
    g_Wt[et][1][n * 128 + k] = __ushort_as_bfloat16(l);
}

// ---------------- aggregation: warp per node, mean -> bf16 hi/lo ----------------
__global__ void __launch_bounds__(256) k_agg(const float4* __restrict__ eu,
                                             const float4* __restrict__ ei) {
    int wid = threadIdx.x >> 5, lane = threadIdx.x & 31;
    int node = blockIdx.x * 8 + wid;
    if (node >= NP) return;
    int et = blockIdx.y;
    float4 acc = make_float4(0.f, 0.f, 0.f, 0.f);
    if (node < NUx) {
        const int* rp  = g_rp[et];
        const int* col = g_col[et];
        const float4* emb = (et == 2) ? ei : eu;
        int b = __ldg(&rp[node]), e = __ldg(&rp[node + 1]);
        int i = b;
        for (; i + 4 <= e; i += 4) {
            int c0 = __ldg(&col[i]),     c1 = __ldg(&col[i + 1]);
            int c2 = __ldg(&col[i + 2]), c3 = __ldg(&col[i + 3]);
            float4 v0 = emb[(size_t)c0 * 32 + lane];
            float4 v1 = emb[(size_t)c1 * 32 + lane];
            float4 v2 = emb[(size_t)c2 * 32 + lane];
            float4 v3 = emb[(size_t)c3 * 32 + lane];
            acc.x += (v0.x + v1.x) + (v2.x + v3.x);
            acc.y += (v0.y + v1.y) + (v2.y + v3.y);
            acc.z += (v0.z + v1.z) + (v2.z + v3.z);
            acc.w += (v0.w + v1.w) + (v2.w + v3.w);
        }
        for (; i < e; i++) {
            int c = __ldg(&col[i]);
            float4 v = emb[(size_t)c * 32 + lane];
            acc.x += v.x; acc.y += v.y; acc.z += v.z; acc.w += v.w;
        }
        float s = 1.0f / (float)max(e - b, 1);
        acc.x *= s; acc.y *= s; acc.z *= s; acc.w *= s;
    }
    unsigned short h0, l0, h1, l1, h2, l2, h3, l3;
    hilo(acc.x, h0, l0); hilo(acc.y, h1, l1); hilo(acc.z, h2, l2); hilo(acc.w, h3, l3);
    uint2 hv = make_uint2((uint32_t)h0 | ((uint32_t)h1 << 16),
                          (uint32_t)h2 | ((uint32_t)h3 << 16));
    uint2 lv = make_uint2((uint32_t)l0 | ((uint32_t)l1 << 16),
                          (uint32_t)l2 | ((uint32_t)l3 << 16));
    ((uint2*)g_Ah[et])[(size_t)node * 32 + lane] = hv;
    ((uint2*)g_Al[et])[(size_t)node * 32 + lane] = lv;
}

// ---------------- layer-0 GEMM (HMMA, chunk-grouped 3-term split) + fused layer-1 proj ----------------
struct GP {
    const __nv_bfloat16 *Ah[2], *Al[2], *Wh[2], *Wl[2];
    const float *b0, *b1;
    const int *dg0, *dg1;
    const float *W1, *pb;          // layer-1 weight [k*128? no: k*16+n], bias [16]
    float* P;
    int N;
};

// SMEM map (bytes): [0,81920) double-buffered groups {Ah,Al,Bh,Bl} x 10240
//                   [81920) b0 512 | [82432) b1 512 | [82944) mk0 512 | [83456) mk1 512
//                   [83968) W1 8192 | [92160) pb 64  -> total 92224
// Epilogue stg (128x132 f32 = 67584) reuses [0,67584).
template <int NET>
__global__ void __launch_bounds__(256, 2) k_hgemm(GP gp) {
    extern __shared__ char S[];
    const int tid  = threadIdx.x;
    const int wid  = tid >> 5, lane = tid & 31;
    const int gId  = lane >> 2, t2 = (lane & 3) * 2;
    const int mrow = (wid & 3) * 32, ncol = (wid >> 2) * 64;
    const int mbase = blockIdx.x * 128;
    const uint32_t sb = smem_u32(S);

    float* sb0  = (float*)(S + 81920);
    float* sb1  = (float*)(S + 82432);
    float* smk0 = (float*)(S + 82944);
    float* smk1 = (float*)(S + 83456);
    float* sw1  = (float*)(S + 83968);
    float* spb  = (float*)(S + 92160);

    if (tid < 128) {
        sb0[tid]  = gp.b0[tid];
        smk0[tid] = (__ldg(&gp.dg0[mbase + tid]) > 0) ? 1.f : 0.f;
        if (NET == 2) {
            sb1[tid]  = gp.b1[tid];
            smk1[tid] = (__ldg(&gp.dg1[mbase + tid]) > 0) ? 1.f : 0.f;
        }
    }
    if (tid < 16) spb[tid] = gp.pb[tid];
#pragma unroll
    for (int i = 0; i < 2; i++) {
        int f = tid + i * 256;
        ((float4*)sw1)[f] = ((const float4*)gp.W1)[f];
    }

    float acc[2][8][4];
#pragma unroll
    for (int mi = 0; mi < 2; mi++)
#pragma unroll
        for (int ni = 0; ni < 8; ni++)
#pragma unroll
            for (int q = 0; q < 4; q++) acc[mi][ni][q] = 0.f;

    const int NG = NET * 4;
    auto load_group = [&](int buf, int g) {
        int et = g >> 2, kc = g & 3;
        const __nv_bfloat16* ah = gp.Ah[et];
        const __nv_bfloat16* al = gp.Al[et];
        const __nv_bfloat16* bh = gp.Wh[et];
        const __nv_bfloat16* bl = gp.Wl[et];
        uint32_t b0a = sb + buf * 40960;
#pragma unroll
        for (int i = 0; i < 2; i++) {
            int idx = tid + i * 256;
            int r = idx >> 2, s4 = idx & 3;
            size_t ga = (size_t)(mbase + r) * 128 + kc * 32 + s4 * 8;
            size_t gw = (size_t)r * 128 + kc * 32 + s4 * 8;
            uint32_t so = r * 80 + s4 * 16;
            cpa16(b0a + so,         ah + ga);
            cpa16(b0a + 10240 + so, al + ga);
            cpa16(b0a + 20480 + so, bh + gw);
            cpa16(b0a + 30720 + so, bl + gw);
        }
    };

    load_group(0, 0);
    CPA_COMMIT();
    for (int g = 0; g < NG; g++) {
        if (g + 1 < NG) { load_group((g + 1) & 1, g + 1); CPA_COMMIT(); CPA_WAIT1(); }
        else            { CPA_WAIT0(); }
        __syncthreads();
        const char* B = S + (g & 1) * 40960;
#pragma unroll
        for (int ks = 0; ks < 2; ks++) {
            const int kb = ks * 16;
            uint32_t ah[2][4], al[2][4];
#pragma unroll
            for (int mi = 0; mi < 2; mi++) {
                const char* p = B + ((mrow + mi * 16 + gId) * 40 + kb + t2) * 2;
                ah[mi][0] = *(const uint32_t*)(p);
                ah[mi][1] = *(const uint32_t*)(p + 640);
                ah[mi][2] = *(const uint32_t*)(p + 16);
                ah[mi][3] = *(const uint32_t*)(p + 656);
                const char* q = p + 10240;
                al[mi][0] = *(const uint32_t*)(q);
                al[mi][1] = *(const uint32_t*)(q + 640);
                al[mi][2] = *(const uint32_t*)(q + 16);
                al[mi][3] = *(const uint32_t*)(q + 656);
            }
#pragma unroll
            for (int ni = 0; ni < 8; ni++) {
                const char* q = B + 20480 + ((ncol + ni * 8 + gId) * 40 + kb + t2) * 2;
                uint32_t bh0 = *(const uint32_t*)(q), bh1 = *(const uint32_t*)(q + 16);
                mma16816(acc[0][ni], ah[0], bh0, bh1);
                mma16816(acc[1][ni], ah[1], bh0, bh1);
                mma16816(acc[0][ni], al[0], bh0, bh1);
                mma16816(acc[1][ni], al[1], bh0, bh1);
                uint32_t bl0 = *(const uint32_t*)(q + 10240), bl1 = *(const uint32_t*)(q + 10256);
                mma16816(acc[0][ni], ah[0], bl0, bl1);
                mma16816(acc[1][ni], ah[1], bl0, bl1);
            }
        }
        __syncthreads();
    }

    // epilogue: bias + mask + relu -> stg (f32, stride 132)
    float* stg = (float*)S;
#pragma unroll
    for (int mi = 0; mi < 2; mi++)
#pragma unroll
        for (int ni = 0; ni < 8; ni++) {
            int r0 = mrow + mi * 16 + gId, c0 = ncol + ni * 8 + t2;
            float m0a = smk0[r0], m0b = smk0[r0 + 8];
            float bx = sb0[c0], by = sb0[c0 + 1];
            float vx0 = acc[mi][ni][0] + m0a * bx, vy0 = acc[mi][ni][1] + m0a * by;
            float vx1 = acc[mi][ni][2] + m0b * bx, vy1 = acc[mi][ni][3] + m0b * by;
            if (NET == 2) {
                float m1a = smk1[r0], m1b = smk1[r0 + 8];
                float cx = sb1[c0], cy = sb1[c0 + 1];
                vx0 += m1a * cx; vy0 += m1a * cy;
                vx1 += m1b * cx; vy1 += m1b * cy;
            }
            *(float2*)&stg[r0 * 132 + c0]       = make_float2(fmaxf(vx0, 0.f), fmaxf(vy0, 0.f));
            *(float2*)&stg[(r0 + 8) * 132 + c0] = make_float2(fmaxf(vx1, 0.f), fmaxf(vy1, 0.f));
        }
    __syncthreads();

    // fused layer-1 projection: P[128x16] = stg @ W1 + pb
    {
        int cp = tid & 7;          // col pair: cols 2cp, 2cp+1
        int rg = tid >> 3;         // rows rg*4 .. rg*4+3
        float pax[4], pay[4];
#pragma unroll
        for (int j = 0; j < 4; j++) { pax[j] = spb[cp * 2]; pay[j] = spb[cp * 2 + 1]; }
#pragma unroll 4
        for (int k = 0; k < 128; k++) {
            float2 w = *(float2*)&sw1[k * 16 + cp * 2];
#pragma unroll
            for (int j = 0; j < 4; j++) {
                float h = stg[(rg * 4 + j) * 132 + k];
                pax[j] += h * w.x;
                pay[j] += h * w.y;
            }
        }
#pragma unroll
        for (int j = 0; j < 4; j++) {
            int gr = mbase + rg * 4 + j;
            if (gr < gp.N)
                *(float2*)&gp.P[(size_t)gr * 16 + cp * 2] = make_float2(pax[j], pay[j]);
        }
    }
}

// ---------------- layer-1 gather-combine into d_out ----------------
__global__ void k_l1(float* __restrict__ out) {
    int t = blockIdx.x * blockDim.x + threadIdx.x;
    if (t >= NUx * 4) return;
    int n = t >> 2, lane = t & 3;
    int b0 = g_rp[0][n], e0 = g_rp[0][n + 1];
    int b2 = g_rp[2][n], e2 = g_rp[2][n + 1];
    float4 a = make_float4(0.f, 0.f, 0.f, 0.f);
    float4 c = make_float4(0.f, 0.f, 0.f, 0.f);
    int eA = b0, eB = b2;
    while (eA < e0 && eB < e2) {
        int s0 = g_col[0][eA], s2 = g_col[2][eB];
        float4 v0 = ((const float4*)g_p_user)[(size_t)s0 * 4 + lane];
        float4 v2 = ((const float4*)g_p_item)[(size_t)s2 * 4 + lane];
        a.x += v0.x; a.y += v0.y; a.z += v0.z; a.w += v0.w;
        c.x += v2.x; c.y += v2.y; c.z += v2.z; c.w += v2.w;
        eA++; eB++;
    }
    for (; eA < e0; eA++) {
        int s0 = g_col[0][eA];
        float4 v0 = ((const float4*)g_p_user)[(size_t)s0 * 4 + lane];
        a.x += v0.x; a.y += v0.y; a.z += v0.z; a.w += v0.w;
    }
    for (; eB < e2; eB++) {
        int s2 = g_col[2][eB];
        float4 v2 = ((const float4*)g_p_item)[(size_t)s2 * 4 + lane];
        c.x += v2.x; c.y += v2.y; c.z += v2.z; c.w += v2.w;
    }
    float i0 = 1.0f / (float)max(e0 - b0, 1);
    float i2 = 1.0f / (float)max(e2 - b2, 1);
    ((float4*)out)[t] = make_float4(a.x * i0 + c.x * i2, a.y * i0 + c.y * i2,
                                    a.z * i0 + c.z * i2, a.w * i0 + c.w * i2);
}

// ---------------- launch ----------------
extern "C" void kernel_launch(void* const* d_in, const int* in_sizes, int n_in,
                              void* d_out, int out_size) {
    const float* embed_user = (const float*)d_in[0];
    const float* embed_item = (const float*)d_in[1];
    const int* src_uu = (const int*)d_in[2];
    const int* dst_uu = (const int*)d_in[3];
    const int* src_ui = (const int*)d_in[4];
    const int* dst_ui = (const int*)d_in[5];
    const int* src_iu = (const int*)d_in[6];
    const int* dst_iu = (const int*)d_in[7];
    const float* W0_uu = (const float*)d_in[8];
    const float* b0_uu = (const float*)d_in[9];
    const float* W0_ui = (const float*)d_in[10];
    const float* b0_ui = (const float*)d_in[11];
    const float* W0_iu = (const float*)d_in[12];
    const float* b0_iu = (const float*)d_in[13];
    const float* W1_uu = (const float*)d_in[14];
    const float* b1_uu = (const float*)d_in[15];
    const float* W1_iu = (const float*)d_in[18];
    const float* b1_iu = (const float*)d_in[19];

    float *p_user, *p_item;
    int* degs;
    __nv_bfloat16 *ah, *al, *wt;
    cudaGetSymbolAddress((void**)&p_user, g_p_user);
    cudaGetSymbolAddress((void**)&p_item, g_p_item);
    cudaGetSymbolAddress((void**)&degs, g_deg);
    cudaGetSymbolAddress((void**)&ah, g_Ah);
    cudaGetSymbolAddress((void**)&al, g_Al);
    cudaGetSymbolAddress((void**)&wt, g_Wt);

    static cudaStream_t s1 = 0;
    static cudaEvent_t eF = 0, eW = 0, eA = 0, eI = 0;
    static bool smem_set = false;
    if (!s1) {
        cudaStreamCreateWithFlags(&s1, cudaStreamNonBlocking);
        cudaEventCreateWithFlags(&eF, cudaEventDisableTiming);
        cudaEventCreateWithFlags(&eW, cudaEventDisableTiming);
        cudaEventCreateWithFlags(&eA, cudaEventDisableTiming);
        cudaEventCreateWithFlags(&eI, cudaEventDisableTiming);
    }
    const int SMEM_G = 92224;
    if (!smem_set) {
        cudaFuncSetAttribute(k_hgemm<2>, cudaFuncAttributeMaxDynamicSharedMemorySize, SMEM_G);
        cudaFuncSetAttribute(k_hgemm<1>, cudaFuncAttributeMaxDynamicSharedMemorySize, SMEM_G);
        smem_set = true;
    }

    // fork: weight conversion on s1, concurrent with CSR build
    cudaEventRecord(eF, 0);
    cudaStreamWaitEvent(s1, eF, 0);
    k_wcvt<<<dim3(128, 3), 128, 0, s1>>>(W0_uu, W0_iu, W0_ui);
    cudaEventRecord(eW, s1);

    // CSR build on stream 0
    k_zero_small<<<NB, 256>>>();
    k_degree<<<EB, 256>>>(dst_uu, dst_ui, dst_iu);
    k_scan1<<<dim3(NB, 3), 256>>>();
    k_scan2<<<3, 512>>>();
    k_scan3<<<dim3(NB, 3), 256>>>();
    k_fill<<<dim3(EB, 3), 256>>>(src_uu, dst_uu, src_ui, dst_ui, src_iu, dst_iu);

    // aggregation (f32 mean -> bf16 hi/lo)
    k_agg<<<dim3((NP + 7) / 8, 3), 256>>>((const float4*)embed_user,
                                          (const float4*)embed_item);
    cudaEventRecord(eA, 0);

    const __nv_bfloat16* Ah0 = ah;                      // uu (dst user)
    const __nv_bfloat16* Ah1 = ah + (size_t)NP * D;     // ui (dst item)
    const __nv_bfloat16* Ah2 = ah + (size_t)2 * NP * D; // iu (dst user)
    const __nv_bfloat16* Al0 = al;
    const __nv_bfloat16* Al1 = al + (size_t)NP * D;
    const __nv_bfloat16* Al2 = al + (size_t)2 * NP * D;
    const __nv_bfloat16* WhUU = wt;
    const __nv_bfloat16* WlUU = wt + 16384;
    const __nv_bfloat16* WhIU = wt + 2 * 16384;
    const __nv_bfloat16* WlIU = wt + 3 * 16384;
    const __nv_bfloat16* WhUI = wt + 4 * 16384;
    const __nv_bfloat16* WlUI = wt + 5 * 16384;

    // user chain on stream 0 (needs weights from s1)
    cudaStreamWaitEvent(0, eW, 0);
    GP gu;
    gu.Ah[0] = Ah0; gu.Ah[1] = Ah2; gu.Al[0] = Al0; gu.Al[1] = Al2;
    gu.Wh[0] = WhUU; gu.Wh[1] = WhIU; gu.Wl[0] = WlUU; gu.Wl[1] = WlIU;
    gu.b0 = b0_uu; gu.b1 = b0_iu;
    gu.dg0 = degs; gu.dg1 = degs + 2 * NP;
    gu.W1 = W1_uu; gu.pb = b1_uu;
    gu.P = p_user; gu.N = NUx;
    k_hgemm<2><<<NP / 128, 256, SMEM_G>>>(gu);

    // item chain on s1 (already has weights; needs agg)
    cudaStreamWaitEvent(s1, eA, 0);
    GP gi;
    gi.Ah[0] = Ah1; gi.Ah[1] = Ah1; gi.Al[0] = Al1; gi.Al[1] = Al1;
    gi.Wh[0] = WhUI; gi.Wh[1] = WhUI; gi.Wl[0] = WlUI; gi.Wl[1] = WlUI;
    gi.b0 = b0_ui; gi.b1 = b0_ui;
    gi.dg0 = degs + NP; gi.dg1 = degs + NP;
    gi.W1 = W1_iu; gi.pb = b1_iu;
    gi.P = p_item; gi.N = NIx;
    k_hgemm<1><<<NP / 128, 256, SMEM_G, s1>>>(gi);
    cudaEventRecord(eI, s1);

    // final gather-combine
    cudaStreamWaitEvent(0, eI, 0);
    k_l1<<<(NUx * 4 + 255) / 256, 256>>>((float*)d_out);
}

// round 6
// speedup vs baseline: 2.2425x; 1.0403x over previous
#include <cuda_runtime.h>
#include <cuda_bf16.h>
#include <cstdint>

#define NUx 100000
#define NIx 100000
#define NP  100096          // padded to multiple of 128
#define NEx 600000
#define D   128
#define DO  16
#define NB  391             // ceil(100000/256)
#define EB  2344            // ceil(600000/256)

// etype ids: 0 = uu (dst user, src user), 1 = ui (dst item, src user), 2 = iu (dst user, src item)
__device__ int g_deg[3][NP];        // padded entries stay 0 (never written)
__device__ int g_cur[3][NUx];
__device__ int g_rp[3][NUx + 1];
__device__ int g_col[3][NEx];
__device__ int g_bsum[3][512];
__device__ __nv_bfloat16 g_Ah[3][NP * D];   // hi bf16 of mean-agg
__device__ __nv_bfloat16 g_Al[3][NP * D];   // lo bf16 residual
__device__ __nv_bfloat16 g_Wt[3][2][D * D]; // [et 0:uu 1:iu 2:ui][0:hi 1:lo][n*128+k]
__device__ float g_p_user[NUx * DO];
__device__ float g_p_item[NIx * DO];

// ---------------- helpers ----------------
__device__ __forceinline__ uint32_t smem_u32(const void* p) {
    uint32_t a;
    asm("{ .reg .u64 t; cvta.to.shared.u64 t, %1; cvt.u32.u64 %0, t; }" : "=r"(a) : "l"(p));
    return a;
}
__device__ __forceinline__ void cpa16(uint32_t dst, const void* src) {
    asm volatile("cp.async.ca.shared.global [%0], [%1], 16;" :: "r"(dst), "l"(src));
}
#define CPA_COMMIT() asm volatile("cp.async.commit_group;" ::: "memory")
#define CPA_WAIT1()  asm volatile("cp.async.wait_group 1;" ::: "memory")
#define CPA_WAIT0()  asm volatile("cp.async.wait_group 0;" ::: "memory")

__device__ __forceinline__ void mma16816(float* c, const uint32_t* a, uint32_t b0, uint32_t b1) {
    asm volatile(
        "mma.sync.aligned.m16n8k16.row.col.f32.bf16.bf16.f32 "
        "{%0,%1,%2,%3}, {%4,%5,%6,%7}, {%8,%9}, {%0,%1,%2,%3};"
        : "+f"(c[0]), "+f"(c[1]), "+f"(c[2]), "+f"(c[3])
        : "r"(a[0]), "r"(a[1]), "r"(a[2]), "r"(a[3]), "r"(b0), "r"(b1));
}
__device__ __forceinline__ void hilo(float v, unsigned short& h, unsigned short& l) {
    __nv_bfloat16 hb = __float2bfloat16(v);
    __nv_bfloat16 lb = __float2bfloat16(v - __bfloat162float(hb));
    h = __bfloat16_as_ushort(hb);
    l = __bfloat16_as_ushort(lb);
}

// ---------------- CSR build (per-etype) ----------------
__global__ void k_zero_small(int et) {
    int i = blockIdx.x * blockDim.x + threadIdx.x;
    if (i < NUx) { g_deg[et][i] = 0; g_cur[et][i] = 0; }
}
__global__ void k_degree(int et, const int* __restrict__ dst) {
    int e = blockIdx.x * blockDim.x + threadIdx.x;
    if (e < NEx) atomicAdd(&g_deg[et][dst[e]], 1);
}
__global__ void k_scan1(int et) {
    __shared__ int s[256];
    int t = threadIdx.x;
    int i = blockIdx.x * 256 + t;
    int v = (i < NUx) ? g_deg[et][i] : 0;
    s[t] = v;
    __syncthreads();
#pragma unroll
    for (int off = 1; off < 256; off <<= 1) {
        int x = (t >= off) ? s[t - off] : 0;
        __syncthreads();
        s[t] += x;
        __syncthreads();
    }
    if (i < NUx) g_rp[et][i] = s[t] - v;
    if (t == 255) g_bsum[et][blockIdx.x] = s[255];
}
__global__ void k_scan2(int et) {
    __shared__ int s[512];
    int t = threadIdx.x;
    int v = (t < NB) ? g_bsum[et][t] : 0;
    s[t] = v;
    __syncthreads();
#pragma unroll
    for (int off = 1; off < 512; off <<= 1) {
        int x = (t >= off) ? s[t - off] : 0;
        __syncthreads();
        s[t] += x;
        __syncthreads();
    }
    if (t < NB) g_bsum[et][t] = s[t] - v;
}
__global__ void k_scan3(int et) {
    int i = blockIdx.x * 256 + threadIdx.x;
    if (i < NUx) g_rp[et][i] += g_bsum[et][blockIdx.x];
    if (i == 0) g_rp[et][NUx] = NEx;
}
__global__ void k_fill(int et, const int* __restrict__ src, const int* __restrict__ dst) {
    int e = blockIdx.x * blockDim.x + threadIdx.x;
    if (e >= NEx) return;
    int dn = dst[e];
    int pos = g_rp[et][dn] + atomicAdd(&g_cur[et][dn], 1);
    g_col[et][pos] = src[e];
}

// ---------------- weight conversion: W[k][n] f32 -> Wt[n][k] bf16 hi/lo ----------------
__global__ void k_wcvt(const float* __restrict__ Wuu, const float* __restrict__ Wiu,
                       const float* __restrict__ Wui) {
    int et = blockIdx.y;            // 0:uu 1:iu 2:ui
    int k = blockIdx.x;             // 0..127
    int n = threadIdx.x;            // 0..127
    const float* W = (et == 0) ? Wuu : (et == 1) ? Wiu : Wui;
    float v = W[k * 128 + n];
    unsigned short h, l;
    hilo(v, h, l);
    g_Wt[et][0][n * 128 + k] = __ushort_as_bfloat16(h);
    g_Wt[et][1][n * 128 + k] = __ushort_as_bfloat16(l);
}

// ---------------- aggregation: warp per node, mean -> bf16 hi/lo ----------------
__global__ void __launch_bounds__(256) k_agg(int et, const float4* __restrict__ emb) {
    int wid = threadIdx.x >> 5, lane = threadIdx.x & 31;
    int node = blockIdx.x * 8 + wid;
    if (node >= NP) return;
    float4 acc = make_float4(0.f, 0.f, 0.f, 0.f);
    if (node < NUx) {
        const int* rp  = g_rp[et];
        const int* col = g_col[et];
        int b = __ldg(&rp[node]), e = __ldg(&rp[node + 1]);
        int i = b;
        for (; i + 4 <= e; i += 4) {
            int c0 = __ldg(&col[i]),     c1 = __ldg(&col[i + 1]);
            int c2 = __ldg(&col[i + 2]), c3 = __ldg(&col[i + 3]);
            float4 v0 = emb[(size_t)c0 * 32 + lane];
            float4 v1 = emb[(size_t)c1 * 32 + lane];
            float4 v2 = emb[(size_t)c2 * 32 + lane];
            float4 v3 = emb[(size_t)c3 * 32 + lane];
            acc.x += (v0.x + v1.x) + (v2.x + v3.x);
            acc.y += (v0.y + v1.y) + (v2.y + v3.y);
            acc.z += (v0.z + v1.z) + (v2.z + v3.z);
            acc.w += (v0.w + v1.w) + (v2.w + v3.w);
        }
        for (; i < e; i++) {
            int c = __ldg(&col[i]);
            float4 v = emb[(size_t)c * 32 + lane];
            acc.x += v.x; acc.y += v.y; acc.z += v.z; acc.w += v.w;
        }
        float s = 1.0f / (float)max(e - b, 1);
        acc.x *= s; acc.y *= s; acc.z *= s; acc.w *= s;
    }
    unsigned short h0, l0, h1, l1, h2, l2, h3, l3;
    hilo(acc.x, h0, l0); hilo(acc.y, h1, l1); hilo(acc.z, h2, l2); hilo(acc.w, h3, l3);
    uint2 hv = make_uint2((uint32_t)h0 | ((uint32_t)h1 << 16),
                          (uint32_t)h2 | ((uint32_t)h3 << 16));
    uint2 lv = make_uint2((uint32_t)l0 | ((uint32_t)l1 << 16),
                          (uint32_t)l2 | ((uint32_t)l3 << 16));
    ((uint2*)g_Ah[et])[(size_t)node * 32 + lane] = hv;
    ((uint2*)g_Al[et])[(size_t)node * 32 + lane] = lv;
}

// ---------------- layer-0 GEMM (HMMA, chunk-grouped 3-term split) + fused layer-1 proj ----------------
struct GP {
    const __nv_bfloat16 *Ah[2], *Al[2], *Wh[2], *Wl[2];
    const float *b0, *b1;
    const int *dg0, *dg1;
    const float *W1, *pb;
    float* P;
    int N;
};

// SMEM map (bytes): [0,81920) double-buffered groups {Ah,Al,Bh,Bl} x 10240
//                   [81920) b0 512 | [82432) b1 512 | [82944) mk0 512 | [83456) mk1 512
//                   [83968) W1 8192 | [92160) pb 64  -> total 92224
template <int NET>
__global__ void __launch_bounds__(256, 2) k_hgemm(GP gp) {
    extern __shared__ char S[];
    const int tid  = threadIdx.x;
    const int wid  = tid >> 5, lane = tid & 31;
    const int gId  = lane >> 2, t2 = (lane & 3) * 2;
    const int mrow = (wid & 3) * 32, ncol = (wid >> 2) * 64;
    const int mbase = blockIdx.x * 128;
    const uint32_t sb = smem_u32(S);

    float* sb0  = (float*)(S + 81920);
    float* sb1  = (float*)(S + 82432);
    float* smk0 = (float*)(S + 82944);
    float* smk1 = (float*)(S + 83456);
    float* sw1  = (float*)(S + 83968);
    float* spb  = (float*)(S + 92160);

    if (tid < 128) {
        sb0[tid]  = gp.b0[tid];
        smk0[tid] = (__ldg(&gp.dg0[mbase + tid]) > 0) ? 1.f : 0.f;
        if (NET == 2) {
            sb1[tid]  = gp.b1[tid];
            smk1[tid] = (__ldg(&gp.dg1[mbase + tid]) > 0) ? 1.f : 0.f;
        }
    }
    if (tid < 16) spb[tid] = gp.pb[tid];
#pragma unroll
    for (int i = 0; i < 2; i++) {
        int f = tid + i * 256;
        ((float4*)sw1)[f] = ((const float4*)gp.W1)[f];
    }

    float acc[2][8][4];
#pragma unroll
    for (int mi = 0; mi < 2; mi++)
#pragma unroll
        for (int ni = 0; ni < 8; ni++)
#pragma unroll
            for (int q = 0; q < 4; q++) acc[mi][ni][q] = 0.f;

    const int NG = NET * 4;
    auto load_group = [&](int buf, int g) {
        int et = g >> 2, kc = g & 3;
        const __nv_bfloat16* ah = gp.Ah[et];
        const __nv_bfloat16* al = gp.Al[et];
        const __nv_bfloat16* bh = gp.Wh[et];
        const __nv_bfloat16* bl = gp.Wl[et];
        uint32_t b0a = sb + buf * 40960;
#pragma unroll
        for (int i = 0; i < 2; i++) {
            int idx = tid + i * 256;
            int r = idx >> 2, s4 = idx & 3;
            size_t ga = (size_t)(mbase + r) * 128 + kc * 32 + s4 * 8;
            size_t gw = (size_t)r * 128 + kc * 32 + s4 * 8;
            uint32_t so = r * 80 + s4 * 16;
            cpa16(b0a + so,         ah + ga);
            cpa16(b0a + 10240 + so, al + ga);
            cpa16(b0a + 20480 + so, bh + gw);
            cpa16(b0a + 30720 + so, bl + gw);
        }
    };

    load_group(0, 0);
    CPA_COMMIT();
    for (int g = 0; g < NG; g++) {
        if (g + 1 < NG) { load_group((g + 1) & 1, g + 1); CPA_COMMIT(); CPA_WAIT1(); }
        else            { CPA_WAIT0(); }
        __syncthreads();
        const char* B = S + (g & 1) * 40960;
#pragma unroll
        for (int ks = 0; ks < 2; ks++) {
            const int kb = ks * 16;
            uint32_t ah[2][4], al[2][4];
#pragma unroll
            for (int mi = 0; mi < 2; mi++) {
                const char* p = B + ((mrow + mi * 16 + gId) * 40 + kb + t2) * 2;
                ah[mi][0] = *(const uint32_t*)(p);
                ah[mi][1] = *(const uint32_t*)(p + 640);
                ah[mi][2] = *(const uint32_t*)(p + 16);
                ah[mi][3] = *(const uint32_t*)(p + 656);
                const char* q = p + 10240;
                al[mi][0] = *(const uint32_t*)(q);
                al[mi][1] = *(const uint32_t*)(q + 640);
                al[mi][2] = *(const uint32_t*)(q + 16);
                al[mi][3] = *(const uint32_t*)(q + 656);
            }
#pragma unroll
            for (int ni = 0; ni < 8; ni++) {
                const char* q = B + 20480 + ((ncol + ni * 8 + gId) * 40 + kb + t2) * 2;
                uint32_t bh0 = *(const uint32_t*)(q), bh1 = *(const uint32_t*)(q + 16);
                mma16816(acc[0][ni], ah[0], bh0, bh1);
                mma16816(acc[1][ni], ah[1], bh0, bh1);
                mma16816(acc[0][ni], al[0], bh0, bh1);
                mma16816(acc[1][ni], al[1], bh0, bh1);
                uint32_t bl0 = *(const uint32_t*)(q + 10240), bl1 = *(const uint32_t*)(q + 10256);
                mma16816(acc[0][ni], ah[0], bl0, bl1);
                mma16816(acc[1][ni], ah[1], bl0, bl1);
            }
        }
        __syncthreads();
    }

    // epilogue: bias + mask + relu -> stg (f32, stride 132)
    float* stg = (float*)S;
#pragma unroll
    for (int mi = 0; mi < 2; mi++)
#pragma unroll
        for (int ni = 0; ni < 8; ni++) {
            int r0 = mrow + mi * 16 + gId, c0 = ncol + ni * 8 + t2;
            float m0a = smk0[r0], m0b = smk0[r0 + 8];
            float bx = sb0[c0], by = sb0[c0 + 1];
            float vx0 = acc[mi][ni][0] + m0a * bx, vy0 = acc[mi][ni][1] + m0a * by;
            float vx1 = acc[mi][ni][2] + m0b * bx, vy1 = acc[mi][ni][3] + m0b * by;
            if (NET == 2) {
                float m1a = smk1[r0], m1b = smk1[r0 + 8];
                float cx = sb1[c0], cy = sb1[c0 + 1];
                vx0 += m1a * cx; vy0 += m1a * cy;
                vx1 += m1b * cx; vy1 += m1b * cy;
            }
            *(float2*)&stg[r0 * 132 + c0]       = make_float2(fmaxf(vx0, 0.f), fmaxf(vy0, 0.f));
            *(float2*)&stg[(r0 + 8) * 132 + c0] = make_float2(fmaxf(vx1, 0.f), fmaxf(vy1, 0.f));
        }
    __syncthreads();

    // fused layer-1 projection: P[128x16] = stg @ W1 + pb
    {
        int cp = tid & 7;
        int rg = tid >> 3;
        float pax[4], pay[4];
#pragma unroll
        for (int j = 0; j < 4; j++) { pax[j] = spb[cp * 2]; pay[j] = spb[cp * 2 + 1]; }
#pragma unroll 4
        for (int k = 0; k < 128; k++) {
            float2 w = *(float2*)&sw1[k * 16 + cp * 2];
#pragma unroll
            for (int j = 0; j < 4; j++) {
                float h = stg[(rg * 4 + j) * 132 + k];
                pax[j] += h * w.x;
                pay[j] += h * w.y;
            }
        }
#pragma unroll
        for (int j = 0; j < 4; j++) {
            int gr = mbase + rg * 4 + j;
            if (gr < gp.N)
                *(float2*)&gp.P[(size_t)gr * 16 + cp * 2] = make_float2(pax[j], pay[j]);
        }
    }
}

// ---------------- layer-1 gather-combine into d_out ----------------
__global__ void k_l1(float* __restrict__ out) {
    int t = blockIdx.x * blockDim.x + threadIdx.x;
    if (t >= NUx * 4) return;
    int n = t >> 2, lane = t & 3;
    int b0 = g_rp[0][n], e0 = g_rp[0][n + 1];
    int b2 = g_rp[2][n], e2 = g_rp[2][n + 1];
    float4 a = make_float4(0.f, 0.f, 0.f, 0.f);
    float4 c = make_float4(0.f, 0.f, 0.f, 0.f);
    int eA = b0, eB = b2;
    while (eA < e0 && eB < e2) {
        int s0 = g_col[0][eA], s2 = g_col[2][eB];
        float4 v0 = ((const float4*)g_p_user)[(size_t)s0 * 4 + lane];
        float4 v2 = ((const float4*)g_p_item)[(size_t)s2 * 4 + lane];
        a.x += v0.x; a.y += v0.y; a.z += v0.z; a.w += v0.w;
        c.x += v2.x; c.y += v2.y; c.z += v2.z; c.w += v2.w;
        eA++; eB++;
    }
    for (; eA < e0; eA++) {
        int s0 = g_col[0][eA];
        float4 v0 = ((const float4*)g_p_user)[(size_t)s0 * 4 + lane];
        a.x += v0.x; a.y += v0.y; a.z += v0.z; a.w += v0.w;
    }
    for (; eB < e2; eB++) {
        int s2 = g_col[2][eB];
        float4 v2 = ((const float4*)g_p_item)[(size_t)s2 * 4 + lane];
        c.x += v2.x; c.y += v2.y; c.z += v2.z; c.w += v2.w;
    }
    float i0 = 1.0f / (float)max(e0 - b0, 1);
    float i2 = 1.0f / (float)max(e2 - b2, 1);
    ((float4*)out)[t] = make_float4(a.x * i0 + c.x * i2, a.y * i0 + c.y * i2,
                                    a.z * i0 + c.z * i2, a.w * i0 + c.w * i2);
}

// ---------------- launch ----------------
extern "C" void kernel_launch(void* const* d_in, const int* in_sizes, int n_in,
                              void* d_out, int out_size) {
    const float* embed_user = (const float*)d_in[0];
    const float* embed_item = (const float*)d_in[1];
    const int* src_uu = (const int*)d_in[2];
    const int* dst_uu = (const int*)d_in[3];
    const int* src_ui = (const int*)d_in[4];
    const int* dst_ui = (const int*)d_in[5];
    const int* src_iu = (const int*)d_in[6];
    const int* dst_iu = (const int*)d_in[7];
    const float* W0_uu = (const float*)d_in[8];
    const float* b0_uu = (const float*)d_in[9];
    const float* W0_ui = (const float*)d_in[10];
    const float* b0_ui = (const float*)d_in[11];
    const float* W0_iu = (const float*)d_in[12];
    const float* b0_iu = (const float*)d_in[13];
    const float* W1_uu = (const float*)d_in[14];
    const float* b1_uu = (const float*)d_in[15];
    const float* W1_iu = (const float*)d_in[18];
    const float* b1_iu = (const float*)d_in[19];

    float *p_user, *p_item;
    int* degs;
    __nv_bfloat16 *ah, *al, *wt;
    cudaGetSymbolAddress((void**)&p_user, g_p_user);
    cudaGetSymbolAddress((void**)&p_item, g_p_item);
    cudaGetSymbolAddress((void**)&degs, g_deg);
    cudaGetSymbolAddress((void**)&ah, g_Ah);
    cudaGetSymbolAddress((void**)&al, g_Al);
    cudaGetSymbolAddress((void**)&wt, g_Wt);

    static cudaStream_t s1 = 0, s2 = 0;
    static cudaEvent_t eF = 0, eW = 0, eA0 = 0, eA1 = 0, eA2 = 0, eI = 0;
    static bool init_done = false;
    const int SMEM_G = 92224;
    if (!init_done) {
        cudaStreamCreateWithFlags(&s1, cudaStreamNonBlocking);
        cudaStreamCreateWithFlags(&s2, cudaStreamNonBlocking);
        cudaEventCreateWithFlags(&eF, cudaEventDisableTiming);
        cudaEventCreateWithFlags(&eW, cudaEventDisableTiming);
        cudaEventCreateWithFlags(&eA0, cudaEventDisableTiming);
        cudaEventCreateWithFlags(&eA1, cudaEventDisableTiming);
        cudaEventCreateWithFlags(&eA2, cudaEventDisableTiming);
        cudaEventCreateWithFlags(&eI, cudaEventDisableTiming);
        cudaFuncSetAttribute(k_hgemm<2>, cudaFuncAttributeMaxDynamicSharedMemorySize, SMEM_G);
        cudaFuncSetAttribute(k_hgemm<1>, cudaFuncAttributeMaxDynamicSharedMemorySize, SMEM_G);
        init_done = true;
    }

    // fork
    cudaEventRecord(eF, 0);
    cudaStreamWaitEvent(s1, eF, 0);
    cudaStreamWaitEvent(s2, eF, 0);

    // wcvt first on s1 (tiny, needed by both GEMMs)
    k_wcvt<<<dim3(128, 3), 128, 0, s1>>>(W0_uu, W0_iu, W0_ui);
    cudaEventRecord(eW, s1);

    // per-etype chains: et0(uu) on s0, et1(ui) on s1, et2(iu) on s2
    const int* srcs[3] = { src_uu, src_ui, src_iu };
    const int* dsts[3] = { dst_uu, dst_ui, dst_iu };
    const float4* embs[3] = { (const float4*)embed_user, (const float4*)embed_user,
                              (const float4*)embed_item };
    cudaStream_t chain[3] = { (cudaStream_t)0, s1, s2 };
    cudaEvent_t  aev[3]   = { eA0, eA1, eA2 };
    for (int et = 0; et < 3; et++) {
        cudaStream_t st = chain[et];
        k_zero_small<<<NB, 256, 0, st>>>(et);
        k_degree<<<EB, 256, 0, st>>>(et, dsts[et]);
        k_scan1<<<NB, 256, 0, st>>>(et);
        k_scan2<<<1, 512, 0, st>>>(et);
        k_scan3<<<NB, 256, 0, st>>>(et);
        k_fill<<<EB, 256, 0, st>>>(et, srcs[et], dsts[et]);
        k_agg<<<(NP + 7) / 8, 256, 0, st>>>(et, embs[et]);
        cudaEventRecord(aev[et], st);
    }

    const __nv_bfloat16* Ah0 = ah;                      // uu (dst user)
    const __nv_bfloat16* Ah1 = ah + (size_t)NP * D;     // ui (dst item)
    const __nv_bfloat16* Ah2 = ah + (size_t)2 * NP * D; // iu (dst user)
    const __nv_bfloat16* Al0 = al;
    const __nv_bfloat16* Al1 = al + (size_t)NP * D;
    const __nv_bfloat16* Al2 = al + (size_t)2 * NP * D;
    const __nv_bfloat16* WhUU = wt;
    const __nv_bfloat16* WlUU = wt + 16384;
    const __nv_bfloat16* WhIU = wt + 2 * 16384;
    const __nv_bfloat16* WlIU = wt + 3 * 16384;
    const __nv_bfloat16* WhUI = wt + 4 * 16384;
    const __nv_bfloat16* WlUI = wt + 5 * 16384;

    // user GEMM on s0: needs agg0 (already on s0), agg2, weights
    cudaStreamWaitEvent(0, eW, 0);
    cudaStreamWaitEvent(0, eA2, 0);
    GP gu;
    gu.Ah[0] = Ah0; gu.Ah[1] = Ah2; gu.Al[0] = Al0; gu.Al[1] = Al2;
    gu.Wh[0] = WhUU; gu.Wh[1] = WhIU; gu.Wl[0] = WlUU; gu.Wl[1] = WlIU;
    gu.b0 = b0_uu; gu.b1 = b0_iu;
    gu.dg0 = degs; gu.dg1 = degs + 2 * NP;
    gu.W1 = W1_uu; gu.pb = b1_uu;
    gu.P = p_user; gu.N = NUx;
    k_hgemm<2><<<NP / 128, 256, SMEM_G>>>(gu);

    // item GEMM on s1: needs agg1 (already on s1), weights (on s1)
    GP gi;
    gi.Ah[0] = Ah1; gi.Ah[1] = Ah1; gi.Al[0] = Al1; gi.Al[1] = Al1;
    gi.Wh[0] = WhUI; gi.Wh[1] = WhUI; gi.Wl[0] = WlUI; gi.Wl[1] = WlUI;
    gi.b0 = b0_ui; gi.b1 = b0_ui;
    gi.dg0 = degs + NP; gi.dg1 = degs + NP;
    gi.W1 = W1_iu; gi.pb = b1_iu;
    gi.P = p_item; gi.N = NIx;
    k_hgemm<1><<<NP / 128, 256, SMEM_G, s1>>>(gi);
    cudaEventRecord(eI, s1);

    // final gather-combine on s0 (rp/col et0 from s0, et2 waited above)
    cudaStreamWaitEvent(0, eI, 0);
    k_l1<<<(NUx * 4 + 255) / 256, 256>>>((float*)d_out);
}

// round 7
// speedup vs baseline: 2.2611x; 1.0083x over previous
#include <cuda_runtime.h>
#include <cuda_bf16.h>
#include <cstdint>

#define NUx 100000
#define NIx 100000
#define NP  100096          // padded to multiple of 128
#define NEx 600000
#define D   128
#define DO  16
#define NB  391             // ceil(100000/256)
#define EB  2344            // ceil(600000/256)

// etype ids: 0 = uu (dst user, src user), 1 = ui (dst item, src user), 2 = iu (dst user, src item)
__device__ int g_deg[3][NP];        // padded entries stay 0 (never written)
__device__ int g_cur[3][NUx];
__device__ int g_rp[3][NUx + 1];
__device__ int g_col[3][NEx];
__device__ int g_bsum[3][512];
__device__ __nv_bfloat16 g_Ah[3][NP * D];   // hi bf16 of mean-agg
__device__ __nv_bfloat16 g_Al[3][NP * D];   // lo bf16 residual
__device__ __nv_bfloat16 g_Wt[3][2][D * D]; // [et 0:uu 1:iu 2:ui][0:hi 1:lo][n*128+k]
__device__ float g_p_user[NUx * DO];
__device__ float g_p_item[NIx * DO];

// ---------------- helpers ----------------
__device__ __forceinline__ uint32_t smem_u32(const void* p) {
    uint32_t a;
    asm("{ .reg .u64 t; cvta.to.shared.u64 t, %1; cvt.u32.u64 %0, t; }" : "=r"(a) : "l"(p));
    return a;
}
__device__ __forceinline__ void cpa16(uint32_t dst, const void* src) {
    asm volatile("cp.async.ca.shared.global [%0], [%1], 16;" :: "r"(dst), "l"(src));
}
#define CPA_COMMIT() asm volatile("cp.async.commit_group;" ::: "memory")
#define CPA_WAIT1()  asm volatile("cp.async.wait_group 1;" ::: "memory")
#define CPA_WAIT0()  asm volatile("cp.async.wait_group 0;" ::: "memory")

__device__ __forceinline__ void mma16816(float* c, const uint32_t* a, uint32_t b0, uint32_t b1) {
    asm volatile(
        "mma.sync.aligned.m16n8k16.row.col.f32.bf16.bf16.f32 "
        "{%0,%1,%2,%3}, {%4,%5,%6,%7}, {%8,%9}, {%0,%1,%2,%3};"
        : "+f"(c[0]), "+f"(c[1]), "+f"(c[2]), "+f"(c[3])
        : "r"(a[0]), "r"(a[1]), "r"(a[2]), "r"(a[3]), "r"(b0), "r"(b1));
}
__device__ __forceinline__ void hilo(float v, unsigned short& h, unsigned short& l) {
    __nv_bfloat16 hb = __float2bfloat16(v);
    __nv_bfloat16 lb = __float2bfloat16(v - __bfloat162float(hb));
    h = __bfloat16_as_ushort(hb);
    l = __bfloat16_as_ushort(lb);
}

// ---------------- CSR build (per-etype) ----------------
__global__ void k_zero_small(int et) {
    int i = blockIdx.x * blockDim.x + threadIdx.x;
    if (i < NUx) { g_deg[et][i] = 0; g_cur[et][i] = 0; }
}
__global__ void k_degree(int et, const int* __restrict__ dst) {
    int e = blockIdx.x * blockDim.x + threadIdx.x;
    if (e < NEx) atomicAdd(&g_deg[et][dst[e]], 1);
}
__global__ void k_scan1(int et) {
    __shared__ int s[256];
    int t = threadIdx.x;
    int i = blockIdx.x * 256 + t;
    int v = (i < NUx) ? g_deg[et][i] : 0;
    s[t] = v;
    __syncthreads();
#pragma unroll
    for (int off = 1; off < 256; off <<= 1) {
        int x = (t >= off) ? s[t - off] : 0;
        __syncthreads();
        s[t] += x;
        __syncthreads();
    }
    if (i < NUx) g_rp[et][i] = s[t] - v;
    if (t == 255) g_bsum[et][blockIdx.x] = s[255];
}
__global__ void k_scan2(int et) {
    __shared__ int s[512];
    int t = threadIdx.x;
    int v = (t < NB) ? g_bsum[et][t] : 0;
    s[t] = v;
    __syncthreads();
#pragma unroll
    for (int off = 1; off < 512; off <<= 1) {
        int x = (t >= off) ? s[t - off] : 0;
        __syncthreads();
        s[t] += x;
        __syncthreads();
    }
    if (t < NB) g_bsum[et][t] = s[t] - v;
}
__global__ void k_scan3(int et) {
    int i = blockIdx.x * 256 + threadIdx.x;
    if (i < NUx) g_rp[et][i] += g_bsum[et][blockIdx.x];
    if (i == 0) g_rp[et][NUx] = NEx;
}
__global__ void k_fill(int et, const int* __restrict__ src, const int* __restrict__ dst) {
    int e = blockIdx.x * blockDim.x + threadIdx.x;
    if (e >= NEx) return;
    int dn = dst[e];
    int pos = g_rp[et][dn] + atomicAdd(&g_cur[et][dn], 1);
    g_col[et][pos] = src[e];
}

// ---------------- weight conversion: W[k][n] f32 -> Wt[n][k] bf16 hi/lo ----------------
__global__ void k_wcvt(const float* __restrict__ Wuu, const float* __restrict__ Wiu,
                       const float* __restrict__ Wui) {
    int et = blockIdx.y;            // 0:uu 1:iu 2:ui
    int k = blockIdx.x;             // 0..127
    int n = threadIdx.x;            // 0..127
    const float* W = (et == 0) ? Wuu : (et == 1) ? Wiu : Wui;
    float v = W[k * 128 + n];
    unsigned short h, l;
    hilo(v, h, l);
    g_Wt[et][0][n * 128 + k] = __ushort_as_bfloat16(h);
    g_Wt[et][1][n * 128 + k] = __ushort_as_bfloat16(l);
}

// ---------------- aggregation: warp per node, mean -> bf16 hi/lo ----------------
__global__ void __launch_bounds__(256) k_agg(int et, const float4* __restrict__ emb) {
    int wid = threadIdx.x >> 5, lane = threadIdx.x & 31;
    int node = blockIdx.x * 8 + wid;
    if (node >= NP) return;
    float4 acc = make_float4(0.f, 0.f, 0.f, 0.f);
    if (node < NUx) {
        const int* rp  = g_rp[et];
        const int* col = g_col[et];
        int b = __ldg(&rp[node]), e = __ldg(&rp[node + 1]);
        int i = b;
        for (; i + 4 <= e; i += 4) {
            int c0 = __ldg(&col[i]),     c1 = __ldg(&col[i + 1]);
            int c2 = __ldg(&col[i + 2]), c3 = __ldg(&col[i + 3]);
            float4 v0 = emb[(size_t)c0 * 32 + lane];
            float4 v1 = emb[(size_t)c1 * 32 + lane];
            float4 v2 = emb[(size_t)c2 * 32 + lane];
            float4 v3 = emb[(size_t)c3 * 32 + lane];
            acc.x += (v0.x + v1.x) + (v2.x + v3.x);
            acc.y += (v0.y + v1.y) + (v2.y + v3.y);
            acc.z += (v0.z + v1.z) + (v2.z + v3.z);
            acc.w += (v0.w + v1.w) + (v2.w + v3.w);
        }
        for (; i < e; i++) {
            int c = __ldg(&col[i]);
            float4 v = emb[(size_t)c * 32 + lane];
            acc.x += v.x; acc.y += v.y; acc.z += v.z; acc.w += v.w;
        }
        float s = 1.0f / (float)max(e - b, 1);
        acc.x *= s; acc.y *= s; acc.z *= s; acc.w *= s;
    }
    unsigned short h0, l0, h1, l1, h2, l2, h3, l3;
    hilo(acc.x, h0, l0); hilo(acc.y, h1, l1); hilo(acc.z, h2, l2); hilo(acc.w, h3, l3);
    uint2 hv = make_uint2((uint32_t)h0 | ((uint32_t)h1 << 16),
                          (uint32_t)h2 | ((uint32_t)h3 << 16));
    uint2 lv = make_uint2((uint32_t)l0 | ((uint32_t)l1 << 16),
                          (uint32_t)l2 | ((uint32_t)l3 << 16));
    ((uint2*)g_Ah[et])[(size_t)node * 32 + lane] = hv;
    ((uint2*)g_Al[et])[(size_t)node * 32 + lane] = lv;
}

// ---------------- layer-0 GEMM (HMMA, chunk-grouped 3-term split) + fused layer-1 proj ----------------
struct GP {
    const __nv_bfloat16 *Ah[2], *Al[2], *Wh[2], *Wl[2];
    const float *b0, *b1;
    const int *dg0, *dg1;
    const float *W1, *pb;
    float* P;
    int N;
};

// SMEM map (bytes): [0,81920) double-buffered groups {Ah,Al,Bh,Bl} x 10240
//                   [81920) b0 512 | [82432) b1 512 | [82944) mk0 512 | [83456) mk1 512
//                   [83968) W1 8192 | [92160) pb 64  -> total 92224
template <int NET>
__global__ void __launch_bounds__(256, 2) k_hgemm(GP gp) {
    extern __shared__ char S[];
    const int tid  = threadIdx.x;
    const int wid  = tid >> 5, lane = tid & 31;
    const int gId  = lane >> 2, t2 = (lane & 3) * 2;
    const int mrow = (wid & 3) * 32, ncol = (wid >> 2) * 64;
    const int mbase = blockIdx.x * 128;
    const uint32_t sb = smem_u32(S);

    float* sb0  = (float*)(S + 81920);
    float* sb1  = (float*)(S + 82432);
    float* smk0 = (float*)(S + 82944);
    float* smk1 = (float*)(S + 83456);
    float* sw1  = (float*)(S + 83968);
    float* spb  = (float*)(S + 92160);

    if (tid < 128) {
        sb0[tid]  = gp.b0[tid];
        smk0[tid] = (__ldg(&gp.dg0[mbase + tid]) > 0) ? 1.f : 0.f;
        if (NET == 2) {
            sb1[tid]  = gp.b1[tid];
            smk1[tid] = (__ldg(&gp.dg1[mbase + tid]) > 0) ? 1.f : 0.f;
        }
    }
    if (tid < 16) spb[tid] = gp.pb[tid];
#pragma unroll
    for (int i = 0; i < 2; i++) {
        int f = tid + i * 256;
        ((float4*)sw1)[f] = ((const float4*)gp.W1)[f];
    }

    float acc[2][8][4];
#pragma unroll
    for (int mi = 0; mi < 2; mi++)
#pragma unroll
        for (int ni = 0; ni < 8; ni++)
#pragma unroll
            for (int q = 0; q < 4; q++) acc[mi][ni][q] = 0.f;

    const int NG = NET * 4;
    auto load_group = [&](int buf, int g) {
        int et = g >> 2, kc = g & 3;
        const __nv_bfloat16* ah = gp.Ah[et];
        const __nv_bfloat16* al = gp.Al[et];
        const __nv_bfloat16* bh = gp.Wh[et];
        const __nv_bfloat16* bl = gp.Wl[et];
        uint32_t b0a = sb + buf * 40960;
#pragma unroll
        for (int i = 0; i < 2; i++) {
            int idx = tid + i * 256;
            int r = idx >> 2, s4 = idx & 3;
            size_t ga = (size_t)(mbase + r) * 128 + kc * 32 + s4 * 8;
            size_t gw = (size_t)r * 128 + kc * 32 + s4 * 8;
            uint32_t so = r * 80 + s4 * 16;
            cpa16(b0a + so,         ah + ga);
            cpa16(b0a + 10240 + so, al + ga);
            cpa16(b0a + 20480 + so, bh + gw);
            cpa16(b0a + 30720 + so, bl + gw);
        }
    };

    load_group(0, 0);
    CPA_COMMIT();
    for (int g = 0; g < NG; g++) {
        if (g + 1 < NG) { load_group((g + 1) & 1, g + 1); CPA_COMMIT(); CPA_WAIT1(); }
        else            { CPA_WAIT0(); }
        __syncthreads();
        const char* B = S + (g & 1) * 40960;
#pragma unroll
        for (int ks = 0; ks < 2; ks++) {
            const int kb = ks * 16;
            uint32_t ah[2][4], al[2][4];
#pragma unroll
            for (int mi = 0; mi < 2; mi++) {
                const char* p = B + ((mrow + mi * 16 + gId) * 40 + kb + t2) * 2;
                ah[mi][0] = *(const uint32_t*)(p);
                ah[mi][1] = *(const uint32_t*)(p + 640);
                ah[mi][2] = *(const uint32_t*)(p + 16);
                ah[mi][3] = *(const uint32_t*)(p + 656);
                const char* q = p + 10240;
                al[mi][0] = *(const uint32_t*)(q);
                al[mi][1] = *(const uint32_t*)(q + 640);
                al[mi][2] = *(const uint32_t*)(q + 16);
                al[mi][3] = *(const uint32_t*)(q + 656);
            }
#pragma unroll
            for (int ni = 0; ni < 8; ni++) {
                const char* q = B + 20480 + ((ncol + ni * 8 + gId) * 40 + kb + t2) * 2;
                uint32_t bh0 = *(const uint32_t*)(q), bh1 = *(const uint32_t*)(q + 16);
                mma16816(acc[0][ni], ah[0], bh0, bh1);
                mma16816(acc[1][ni], ah[1], bh0, bh1);
                mma16816(acc[0][ni], al[0], bh0, bh1);
                mma16816(acc[1][ni], al[1], bh0, bh1);
                uint32_t bl0 = *(const uint32_t*)(q + 10240), bl1 = *(const uint32_t*)(q + 10256);
                mma16816(acc[0][ni], ah[0], bl0, bl1);
                mma16816(acc[1][ni], ah[1], bl0, bl1);
            }
        }
        __syncthreads();
    }

    // epilogue: bias + mask + relu -> stg (f32, stride 132)
    float* stg = (float*)S;
#pragma unroll
    for (int mi = 0; mi < 2; mi++)
#pragma unroll
        for (int ni = 0; ni < 8; ni++) {
            int r0 = mrow + mi * 16 + gId, c0 = ncol + ni * 8 + t2;
            float m0a = smk0[r0], m0b = smk0[r0 + 8];
            float bx = sb0[c0], by = sb0[c0 + 1];
            float vx0 = acc[mi][ni][0] + m0a * bx, vy0 = acc[mi][ni][1] + m0a * by;
            float vx1 = acc[mi][ni][2] + m0b * bx, vy1 = acc[mi][ni][3] + m0b * by;
            if (NET == 2) {
                float m1a = smk1[r0], m1b = smk1[r0 + 8];
                float cx = sb1[c0], cy = sb1[c0 + 1];
                vx0 += m1a * cx; vy0 += m1a * cy;
                vx1 += m1b * cx; vy1 += m1b * cy;
            }
            *(float2*)&stg[r0 * 132 + c0]       = make_float2(fmaxf(vx0, 0.f), fmaxf(vy0, 0.f));
            *(float2*)&stg[(r0 + 8) * 132 + c0] = make_float2(fmaxf(vx1, 0.f), fmaxf(vy1, 0.f));
        }
    __syncthreads();

    // fused layer-1 projection: P[128x16] = stg @ W1 + pb
    {
        int cp = tid & 7;
        int rg = tid >> 3;
        float pax[4], pay[4];
#pragma unroll
        for (int j = 0; j < 4; j++) { pax[j] = spb[cp * 2]; pay[j] = spb[cp * 2 + 1]; }
#pragma unroll 4
        for (int k = 0; k < 128; k++) {
            float2 w = *(float2*)&sw1[k * 16 + cp * 2];
#pragma unroll
            for (int j = 0; j < 4; j++) {
                float h = stg[(rg * 4 + j) * 132 + k];
                pax[j] += h * w.x;
                pay[j] += h * w.y;
            }
        }
#pragma unroll
        for (int j = 0; j < 4; j++) {
            int gr = mbase + rg * 4 + j;
            if (gr < gp.N)
                *(float2*)&gp.P[(size_t)gr * 16 + cp * 2] = make_float2(pax[j], pay[j]);
        }
    }
}

// ---------------- layer-1 gather-combine, split in two halves ----------------
// k_l1i: out = mean_iu(p_item)   (runs early, hidden under user GEMM)
__global__ void k_l1i(float* __restrict__ out) {
    int t = blockIdx.x * blockDim.x + threadIdx.x;
    if (t >= NUx * 4) return;
    int n = t >> 2, lane = t & 3;
    int b2 = g_rp[2][n], e2 = g_rp[2][n + 1];
    float4 c = make_float4(0.f, 0.f, 0.f, 0.f);
    for (int i = b2; i < e2; i++) {
        int s2 = __ldg(&g_col[2][i]);
        float4 v = ((const float4*)g_p_item)[(size_t)s2 * 4 + lane];
        c.x += v.x; c.y += v.y; c.z += v.z; c.w += v.w;
    }
    float i2 = 1.0f / (float)max(e2 - b2, 1);
    ((float4*)out)[t] = make_float4(c.x * i2, c.y * i2, c.z * i2, c.w * i2);
}
// k_l1u: out += mean_uu(p_user)  (critical-path tail)
__global__ void k_l1u(float* __restrict__ out) {
    int t = blockIdx.x * blockDim.x + threadIdx.x;
    if (t >= NUx * 4) return;
    int n = t >> 2, lane = t & 3;
    int b0 = g_rp[0][n], e0 = g_rp[0][n + 1];
    float4 a = make_float4(0.f, 0.f, 0.f, 0.f);
    for (int i = b0; i < e0; i++) {
        int s0 = __ldg(&g_col[0][i]);
        float4 v = ((const float4*)g_p_user)[(size_t)s0 * 4 + lane];
        a.x += v.x; a.y += v.y; a.z += v.z; a.w += v.w;
    }
    float i0 = 1.0f / (float)max(e0 - b0, 1);
    float4 o = ((float4*)out)[t];
    ((float4*)out)[t] = make_float4(o.x + a.x * i0, o.y + a.y * i0,
                                    o.z + a.z * i0, o.w + a.w * i0);
}

// ---------------- launch ----------------
extern "C" void kernel_launch(void* const* d_in, const int* in_sizes, int n_in,
                              void* d_out, int out_size) {
    const float* embed_user = (const float*)d_in[0];
    const float* embed_item = (const float*)d_in[1];
    const int* src_uu = (const int*)d_in[2];
    const int* dst_uu = (const int*)d_in[3];
    const int* src_ui = (const int*)d_in[4];
    const int* dst_ui = (const int*)d_in[5];
    const int* src_iu = (const int*)d_in[6];
    const int* dst_iu = (const int*)d_in[7];
    const float* W0_uu = (const float*)d_in[8];
    const float* b0_uu = (const float*)d_in[9];
    const float* W0_ui = (const float*)d_in[10];
    const float* b0_ui = (const float*)d_in[11];
    const float* W0_iu = (const float*)d_in[12];
    const float* b0_iu = (const float*)d_in[13];
    const float* W1_uu = (const float*)d_in[14];
    const float* b1_uu = (const float*)d_in[15];
    const float* W1_iu = (const float*)d_in[18];
    const float* b1_iu = (const float*)d_in[19];

    float *p_user, *p_item;
    int* degs;
    __nv_bfloat16 *ah, *al, *wt;
    cudaGetSymbolAddress((void**)&p_user, g_p_user);
    cudaGetSymbolAddress((void**)&p_item, g_p_item);
    cudaGetSymbolAddress((void**)&degs, g_deg);
    cudaGetSymbolAddress((void**)&ah, g_Ah);
    cudaGetSymbolAddress((void**)&al, g_Al);
    cudaGetSymbolAddress((void**)&wt, g_Wt);

    static cudaStream_t s1 = 0, s2 = 0;
    static cudaEvent_t eF = 0, eW = 0, eA0 = 0, eA2 = 0, eLi = 0;
    static bool init_done = false;
    const int SMEM_G = 92224;
    if (!init_done) {
        cudaStreamCreateWithFlags(&s1, cudaStreamNonBlocking);
        cudaStreamCreateWithFlags(&s2, cudaStreamNonBlocking);
        cudaEventCreateWithFlags(&eF, cudaEventDisableTiming);
        cudaEventCreateWithFlags(&eW, cudaEventDisableTiming);
        cudaEventCreateWithFlags(&eA0, cudaEventDisableTiming);
        cudaEventCreateWithFlags(&eA2, cudaEventDisableTiming);
        cudaEventCreateWithFlags(&eLi, cudaEventDisableTiming);
        cudaFuncSetAttribute(k_hgemm<2>, cudaFuncAttributeMaxDynamicSharedMemorySize, SMEM_G);
        cudaFuncSetAttribute(k_hgemm<1>, cudaFuncAttributeMaxDynamicSharedMemorySize, SMEM_G);
        init_done = true;
    }

    // fork
    cudaEventRecord(eF, 0);
    cudaStreamWaitEvent(s1, eF, 0);
    cudaStreamWaitEvent(s2, eF, 0);

    // s1: wcvt (tiny) + CSR for et1 (ui); agg1 deferred until critical aggs finish
    k_wcvt<<<dim3(128, 3), 128, 0, s1>>>(W0_uu, W0_iu, W0_ui);
    cudaEventRecord(eW, s1);
    k_zero_small<<<NB, 256, 0, s1>>>(1);
    k_degree<<<EB, 256, 0, s1>>>(1, dst_ui);
    k_scan1<<<NB, 256, 0, s1>>>(1);
    k_scan2<<<1, 512, 0, s1>>>(1);
    k_scan3<<<NB, 256, 0, s1>>>(1);
    k_fill<<<EB, 256, 0, s1>>>(1, src_ui, dst_ui);

    // s0: CSR + agg for et0 (uu)
    k_zero_small<<<NB, 256>>>(0);
    k_degree<<<EB, 256>>>(0, dst_uu);
    k_scan1<<<NB, 256>>>(0);
    k_scan2<<<1, 512>>>(0);
    k_scan3<<<NB, 256>>>(0);
    k_fill<<<EB, 256>>>(0, src_uu, dst_uu);
    k_agg<<<(NP + 7) / 8, 256>>>(0, (const float4*)embed_user);
    cudaEventRecord(eA0, 0);

    // s2: CSR + agg for et2 (iu)
    k_zero_small<<<NB, 256, 0, s2>>>(2);
    k_degree<<<EB, 256, 0, s2>>>(2, dst_iu);
    k_scan1<<<NB, 256, 0, s2>>>(2);
    k_scan2<<<1, 512, 0, s2>>>(2);
    k_scan3<<<NB, 256, 0, s2>>>(2);
    k_fill<<<EB, 256, 0, s2>>>(2, src_iu, dst_iu);
    k_agg<<<(NP + 7) / 8, 256, 0, s2>>>(2, (const float4*)embed_item);
    cudaEventRecord(eA2, s2);

    const __nv_bfloat16* Ah0 = ah;
    const __nv_bfloat16* Ah1 = ah + (size_t)NP * D;
    const __nv_bfloat16* Ah2 = ah + (size_t)2 * NP * D;
    const __nv_bfloat16* Al0 = al;
    const __nv_bfloat16* Al1 = al + (size_t)NP * D;
    const __nv_bfloat16* Al2 = al + (size_t)2 * NP * D;
    const __nv_bfloat16* WhUU = wt;
    const __nv_bfloat16* WlUU = wt + 16384;
    const __nv_bfloat16* WhIU = wt + 2 * 16384;
    const __nv_bfloat16* WlIU = wt + 3 * 16384;
    const __nv_bfloat16* WhUI = wt + 4 * 16384;
    const __nv_bfloat16* WlUI = wt + 5 * 16384;

    // user GEMM on s0: needs agg0 (s0), agg2, weights
    cudaStreamWaitEvent(0, eW, 0);
    cudaStreamWaitEvent(0, eA2, 0);
    GP gu;
    gu.Ah[0] = Ah0; gu.Ah[1] = Ah2; gu.Al[0] = Al0; gu.Al[1] = Al2;
    gu.Wh[0] = WhUU; gu.Wh[1] = WhIU; gu.Wl[0] = WlUU; gu.Wl[1] = WlIU;
    gu.b0 = b0_uu; gu.b1 = b0_iu;
    gu.dg0 = degs; gu.dg1 = degs + 2 * NP;
    gu.W1 = W1_uu; gu.pb = b1_uu;
    gu.P = p_user; gu.N = NUx;
    k_hgemm<2><<<NP / 128, 256, SMEM_G>>>(gu);

    // s1: deferred agg1 (after critical aggs), then item GEMM + k_l1i, all hidden under user GEMM
    cudaStreamWaitEvent(s1, eA0, 0);
    cudaStreamWaitEvent(s1, eA2, 0);
    k_agg<<<(NP + 7) / 8, 256, 0, s1>>>(1, (const float4*)embed_user);
    GP gi;
    gi.Ah[0] = Ah1; gi.Ah[1] = Ah1; gi.Al[0] = Al1; gi.Al[1] = Al1;
    gi.Wh[0] = WhUI; gi.Wh[1] = WhUI; gi.Wl[0] = WlUI; gi.Wl[1] = WlUI;
    gi.b0 = b0_ui; gi.b1 = b0_ui;
    gi.dg0 = degs + NP; gi.dg1 = degs + NP;
    gi.W1 = W1_iu; gi.pb = b1_iu;
    gi.P = p_item; gi.N = NIx;
    k_hgemm<1><<<NP / 128, 256, SMEM_G, s1>>>(gi);
    k_l1i<<<(NUx * 4 + 255) / 256, 256, 0, s1>>>((float*)d_out);
    cudaEventRecord(eLi, s1);

    // critical-path tail: add user half
    cudaStreamWaitEvent(0, eLi, 0);
    k_l1u<<<(NUx * 4 + 255) / 256, 256>>>((float*)d_out);
}

// round 9
// speedup vs baseline: 2.3113x; 1.0222x over previous
#include <cuda_runtime.h>
#include <cuda_bf16.h>
#include <cstdint>

#define NUx 100000
#define NIx 100000
#define NP  100096          // padded to multiple of 128
#define NEx 600000
#define D   128
#define DO  16
#define NB  391             // ceil(100000/256)
#define EB  2344            // ceil(600000/256)

// etype ids: 0 = uu (dst user, src user), 1 = ui (dst item, src user), 2 = iu (dst user, src item)
__device__ int g_deg[3][NP];        // padded entries stay 0 (never written)
__device__ int g_cur[3][NUx];
__device__ int g_rp[3][NUx + 1];
__device__ int g_col[3][NEx];
__device__ int g_bsum[3][512];
__device__ __nv_bfloat16 g_Ah[3][NP * D];   // hi bf16 of mean-agg
__device__ __nv_bfloat16 g_Al[3][NP * D];   // lo bf16 residual
__device__ __nv_bfloat16 g_Wt[3][2][D * D]; // [et 0:uu 1:iu 2:ui][0:hi 1:lo][n*128+k]
__device__ float g_p_user[NUx * DO];
__device__ float g_p_item[NIx * DO];

// ---------------- helpers ----------------
__device__ __forceinline__ uint32_t smem_u32(const void* p) {
    uint32_t a;
    asm("{ .reg .u64 t; cvta.to.shared.u64 t, %1; cvt.u32.u64 %0, t; }" : "=r"(a) : "l"(p));
    return a;
}
__device__ __forceinline__ void cpa16(uint32_t dst, const void* src) {
    asm volatile("cp.async.ca.shared.global [%0], [%1], 16;" :: "r"(dst), "l"(src));
}
#define CPA_COMMIT() asm volatile("cp.async.commit_group;" ::: "memory")
#define CPA_WAIT1()  asm volatile("cp.async.wait_group 1;" ::: "memory")
#define CPA_WAIT0()  asm volatile("cp.async.wait_group 0;" ::: "memory")

__device__ __forceinline__ void mma16816(float* c, const uint32_t* a, uint32_t b0, uint32_t b1) {
    asm volatile(
        "mma.sync.aligned.m16n8k16.row.col.f32.bf16.bf16.f32 "
        "{%0,%1,%2,%3}, {%4,%5,%6,%7}, {%8,%9}, {%0,%1,%2,%3};"
        : "+f"(c[0]), "+f"(c[1]), "+f"(c[2]), "+f"(c[3])
        : "r"(a[0]), "r"(a[1]), "r"(a[2]), "r"(a[3]), "r"(b0), "r"(b1));
}
__device__ __forceinline__ void ldsm4(uint32_t* r, uint32_t addr) {
    asm volatile("ldmatrix.sync.aligned.m8n8.x4.shared.b16 {%0,%1,%2,%3}, [%4];"
                 : "=r"(r[0]), "=r"(r[1]), "=r"(r[2]), "=r"(r[3]) : "r"(addr));
}
__device__ __forceinline__ void hilo(float v, unsigned short& h, unsigned short& l) {
    __nv_bfloat16 hb = __float2bfloat16(v);
    __nv_bfloat16 lb = __float2bfloat16(v - __bfloat162float(hb));
    h = __bfloat16_as_ushort(hb);
    l = __bfloat16_as_ushort(lb);
}

// ---------------- CSR build (batched over 3 etypes) ----------------
__global__ void k_zero_small() {
    int i = blockIdx.x * blockDim.x + threadIdx.x;
    if (i < NUx) {
#pragma unroll
        for (int y = 0; y < 3; y++) { g_deg[y][i] = 0; g_cur[y][i] = 0; }
    }
}
__global__ void k_degree(const int* __restrict__ duu, const int* __restrict__ dui,
                         const int* __restrict__ diu) {
    int e = blockIdx.x * blockDim.x + threadIdx.x;
    if (e < NEx) {
        atomicAdd(&g_deg[0][duu[e]], 1);
        atomicAdd(&g_deg[1][dui[e]], 1);
        atomicAdd(&g_deg[2][diu[e]], 1);
    }
}
__global__ void k_scan1() {
    __shared__ int s[256];
    int y = blockIdx.y, t = threadIdx.x;
    int i = blockIdx.x * 256 + t;
    int v = (i < NUx) ? g_deg[y][i] : 0;
    s[t] = v;
    __syncthreads();
#pragma unroll
    for (int off = 1; off < 256; off <<= 1) {
        int x = (t >= off) ? s[t - off] : 0;
        __syncthreads();
        s[t] += x;
        __syncthreads();
    }
    if (i < NUx) g_rp[y][i] = s[t] - v;
    if (t == 255) g_bsum[y][blockIdx.x] = s[255];
}
__global__ void k_scan2() {
    __shared__ int s[512];
    int y = blockIdx.x, t = threadIdx.x;
    int v = (t < NB) ? g_bsum[y][t] : 0;
    s[t] = v;
    __syncthreads();
#pragma unroll
    for (int off = 1; off < 512; off <<= 1) {
        int x = (t >= off) ? s[t - off] : 0;
        __syncthreads();
        s[t] += x;
        __syncthreads();
    }
    if (t < NB) g_bsum[y][t] = s[t] - v;
}
__global__ void k_scan3() {
    int y = blockIdx.y;
    int i = blockIdx.x * 256 + threadIdx.x;
    if (i < NUx) g_rp[y][i] += g_bsum[y][blockIdx.x];
    if (i == 0) g_rp[y][NUx] = NEx;
}
__global__ void k_fill(const int* __restrict__ suu, const int* __restrict__ duu,
                       const int* __restrict__ sui, const int* __restrict__ dui,
                       const int* __restrict__ siu, const int* __restrict__ diu) {
    int e = blockIdx.x * blockDim.x + threadIdx.x;
    if (e >= NEx) return;
    int y = blockIdx.y;
    const int* s; const int* d;
    if (y == 0)      { s = suu; d = duu; }
    else if (y == 1) { s = sui; d = dui; }
    else             { s = siu; d = diu; }
    int dn = d[e];
    int pos = g_rp[y][dn] + atomicAdd(&g_cur[y][dn], 1);
    g_col[y][pos] = s[e];
}

// ---------------- weight conversion: W[k][n] f32 -> Wt[n][k] bf16 hi/lo ----------------
__global__ void k_wcvt(const float* __restrict__ Wuu, const float* __restrict__ Wiu,
                       const float* __restrict__ Wui) {
    int et = blockIdx.y;
    int k = blockIdx.x;
    int n = threadIdx.x;
    const float* W = (et == 0) ? Wuu : (et == 1) ? Wiu : Wui;
    float v = W[k * 128 + n];
    unsigned short h, l;
    hilo(v, h, l);
    g_Wt[et][0][n * 128 + k] = __ushort_as_bfloat16(h);
    g_Wt[et][1][n * 128 + k] = __ushort_as_bfloat16(l);
}

// ---------------- aggregation: warp per node, mean -> bf16 hi/lo ----------------
__global__ void __launch_bounds__(256) k_agg(int et, const float4* __restrict__ emb) {
    int wid = threadIdx.x >> 5, lane = threadIdx.x & 31;
    int node = blockIdx.x * 8 + wid;
    if (node >= NP) return;
    float4 acc = make_float4(0.f, 0.f, 0.f, 0.f);
    if (node < NUx) {
        const int* rp  = g_rp[et];
        const int* col = g_col[et];
        int b = __ldg(&rp[node]), e = __ldg(&rp[node + 1]);
        int i = b;
        for (; i + 4 <= e; i += 4) {
            int c0 = __ldg(&col[i]),     c1 = __ldg(&col[i + 1]);
            int c2 = __ldg(&col[i + 2]), c3 = __ldg(&col[i + 3]);
            float4 v0 = emb[(size_t)c0 * 32 + lane];
            float4 v1 = emb[(size_t)c1 * 32 + lane];
            float4 v2 = emb[(size_t)c2 * 32 + lane];
            float4 v3 = emb[(size_t)c3 * 32 + lane];
            acc.x += (v0.x + v1.x) + (v2.x + v3.x);
            acc.y += (v0.y + v1.y) + (v2.y + v3.y);
            acc.z += (v0.z + v1.z) + (v2.z + v3.z);
            acc.w += (v0.w + v1.w) + (v2.w + v3.w);
        }
        for (; i < e; i++) {
            int c = __ldg(&col[i]);
            float4 v = emb[(size_t)c * 32 + lane];
            acc.x += v.x; acc.y += v.y; acc.z += v.z; acc.w += v.w;
        }
        float s = 1.0f / (float)max(e - b, 1);
        acc.x *= s; acc.y *= s; acc.z *= s; acc.w *= s;
    }
    unsigned short h0, l0, h1, l1, h2, l2, h3, l3;
    hilo(acc.x, h0, l0); hilo(acc.y, h1, l1); hilo(acc.z, h2, l2); hilo(acc.w, h3, l3);
    uint2 hv = make_uint2((uint32_t)h0 | ((uint32_t)h1 << 16),
                          (uint32_t)h2 | ((uint32_t)h3 << 16));
    uint2 lv = make_uint2((uint32_t)l0 | ((uint32_t)l1 << 16),
                          (uint32_t)l2 | ((uint32_t)l3 << 16));
    ((uint2*)g_Ah[et])[(size_t)node * 32 + lane] = hv;
    ((uint2*)g_Al[et])[(size_t)node * 32 + lane] = lv;
}

// ---------------- layer-0 GEMM (HMMA + ldmatrix, 3-term split) + fused layer-1 proj ----------------
struct GP {
    const __nv_bfloat16 *Ah[2], *Al[2], *Wh[2], *Wl[2];
    const float *b0, *b1;
    const int *dg0, *dg1;
    const float *W1, *pb;
    float* P;
    int N;
};

// SMEM map (bytes): [0,81920) double-buffered groups {Ah,Al,Bh,Bl} x 10240
//                   [81920) b0 512 | [82432) b1 512 | [82944) mk0 512 | [83456) mk1 512
//                   [83968) W1 8192 | [92160) pb 64  -> total 92224
template <int NET>
__global__ void __launch_bounds__(256, 2) k_hgemm(GP gp) {
    extern __shared__ char S[];
    const int tid  = threadIdx.x;
    const int wid  = tid >> 5, lane = tid & 31;
    const int gId  = lane >> 2, t2 = (lane & 3) * 2;
    const int mrow = (wid & 3) * 32, ncol = (wid >> 2) * 64;
    const int mbase = blockIdx.x * 128;
    const uint32_t sb = smem_u32(S);

    float* sb0  = (float*)(S + 81920);
    float* sb1  = (float*)(S + 82432);
    float* smk0 = (float*)(S + 82944);
    float* smk1 = (float*)(S + 83456);
    float* sw1  = (float*)(S + 83968);
    float* spb  = (float*)(S + 92160);

    if (tid < 128) {
        sb0[tid]  = gp.b0[tid];
        smk0[tid] = (__ldg(&gp.dg0[mbase + tid]) > 0) ? 1.f : 0.f;
        if (NET == 2) {
            sb1[tid]  = gp.b1[tid];
            smk1[tid] = (__ldg(&gp.dg1[mbase + tid]) > 0) ? 1.f : 0.f;
        }
    }
    if (tid < 16) spb[tid] = gp.pb[tid];
#pragma unroll
    for (int i = 0; i < 2; i++) {
        int f = tid + i * 256;
        ((float4*)sw1)[f] = ((const float4*)gp.W1)[f];
    }

    float acc[2][8][4];
#pragma unroll
    for (int mi = 0; mi < 2; mi++)
#pragma unroll
        for (int ni = 0; ni < 8; ni++)
#pragma unroll
            for (int q = 0; q < 4; q++) acc[mi][ni][q] = 0.f;

    const int NG = NET * 4;
    auto load_group = [&](int buf, int g) {
        int et = g >> 2, kc = g & 3;
        const __nv_bfloat16* ah = gp.Ah[et];
        const __nv_bfloat16* al = gp.Al[et];
        const __nv_bfloat16* bh = gp.Wh[et];
        const __nv_bfloat16* bl = gp.Wl[et];
        uint32_t b0a = sb + buf * 40960;
#pragma unroll
        for (int i = 0; i < 2; i++) {
            int idx = tid + i * 256;
            int r = idx >> 2, s4 = idx & 3;
            size_t ga = (size_t)(mbase + r) * 128 + kc * 32 + s4 * 8;
            size_t gw = (size_t)r * 128 + kc * 32 + s4 * 8;
            uint32_t so = r * 80 + s4 * 16;
            cpa16(b0a + so,         ah + ga);
            cpa16(b0a + 10240 + so, al + ga);
            cpa16(b0a + 20480 + so, bh + gw);
            cpa16(b0a + 30720 + so, bl + gw);
        }
    };

    // ldmatrix lane addressing
    const int lr = lane & 7, lg = lane >> 3;

    load_group(0, 0);
    CPA_COMMIT();
    for (int g = 0; g < NG; g++) {
        if (g + 1 < NG) { load_group((g + 1) & 1, g + 1); CPA_COMMIT(); CPA_WAIT1(); }
        else            { CPA_WAIT0(); }
        __syncthreads();
        const uint32_t Bs = sb + (g & 1) * 40960;
#pragma unroll
        for (int ks = 0; ks < 2; ks++) {
            const int kb = ks * 16;
            // A fragments: x4 tiles {r0:(m0-7,k0-7) r1:(m8-15,k0-7) r2:(m0-7,k8-15) r3:(m8-15,k8-15)}
            const int arow = (lg & 1) * 8 + lr;
            const int acol = kb + (lg >> 1) * 8;
            uint32_t ah0[4], ah1[4], al0[4], al1[4];
            uint32_t a0 = Bs + ((mrow + arow) * 40 + acol) * 2;
            uint32_t a1 = a0 + 16 * 80;
            ldsm4(ah0, a0);
            ldsm4(ah1, a1);
            ldsm4(al0, a0 + 10240);
            ldsm4(al1, a1 + 10240);
            // B fragments: per ni-pair, x4 tiles {b0(ni),b1(ni),b0(ni+1),b1(ni+1)}
            const int brow = (lg >> 1) * 8 + lr;
            const int bcol = kb + (lg & 1) * 8;
#pragma unroll
            for (int np = 0; np < 4; np++) {
                uint32_t bh[4], bl[4];
                uint32_t bo = Bs + 20480 + ((ncol + np * 16 + brow) * 40 + bcol) * 2;
                ldsm4(bh, bo);
                ldsm4(bl, bo + 10240);
                mma16816(acc[0][2 * np],     ah0, bh[0], bh[1]);
                mma16816(acc[1][2 * np],     ah1, bh[0], bh[1]);
                mma16816(acc[0][2 * np],     al0, bh[0], bh[1]);
                mma16816(acc[1][2 * np],     al1, bh[0], bh[1]);
                mma16816(acc[0][2 * np],     ah0, bl[0], bl[1]);
                mma16816(acc[1][2 * np],     ah1, bl[0], bl[1]);
                mma16816(acc[0][2 * np + 1], ah0, bh[2], bh[3]);
                mma16816(acc[1][2 * np + 1], ah1, bh[2], bh[3]);
                mma16816(acc[0][2 * np + 1], al0, bh[2], bh[3]);
                mma16816(acc[1][2 * np + 1], al1, bh[2], bh[3]);
                mma16816(acc[0][2 * np + 1], ah0, bl[2], bl[3]);
                mma16816(acc[1][2 * np + 1], ah1, bl[2], bl[3]);
            }
        }
        __syncthreads();
    }

    // epilogue: bias + mask + relu -> stg (f32, stride 132)
    float* stg = (float*)S;
#pragma unroll
    for (int mi = 0; mi < 2; mi++)
#pragma unroll
        for (int ni = 0; ni < 8; ni++) {
            int r0 = mrow + mi * 16 + gId, c0 = ncol + ni * 8 + t2;
            float m0a = smk0[r0], m0b = smk0[r0 + 8];
            float bx = sb0[c0], by = sb0[c0 + 1];
            float vx0 = acc[mi][ni][0] + m0a * bx, vy0 = acc[mi][ni][1] + m0a * by;
            float vx1 = acc[mi][ni][2] + m0b * bx, vy1 = acc[mi][ni][3] + m0b * by;
            if (NET == 2) {
                float m1a = smk1[r0], m1b = smk1[r0 + 8];
                float cx = sb1[c0], cy = sb1[c0 + 1];
                vx0 += m1a * cx; vy0 += m1a * cy;
                vx1 += m1b * cx; vy1 += m1b * cy;
            }
            *(float2*)&stg[r0 * 132 + c0]       = make_float2(fmaxf(vx0, 0.f), fmaxf(vy0, 0.f));
            *(float2*)&stg[(r0 + 8) * 132 + c0] = make_float2(fmaxf(vx1, 0.f), fmaxf(vy1, 0.f));
        }
    __syncthreads();

    // fused layer-1 projection: P[128x16] = stg @ W1 + pb
    {
        int cp = tid & 7;
        int rg = tid >> 3;
        float pax[4], pay[4];
#pragma unroll
        for (int j = 0; j < 4; j++) { pax[j] = spb[cp * 2]; pay[j] = spb[cp * 2 + 1]; }
#pragma unroll 4
        for (int k = 0; k < 128; k++) {
            float2 w = *(float2*)&sw1[k * 16 + cp * 2];
#pragma unroll
            for (int j = 0; j < 4; j++) {
                float h = stg[(rg * 4 + j) * 132 + k];
                pax[j] += h * w.x;
                pay[j] += h * w.y;
            }
        }
#pragma unroll
        for (int j = 0; j < 4; j++) {
            int gr = mbase + rg * 4 + j;
            if (gr < gp.N)
                *(float2*)&gp.P[(size_t)gr * 16 + cp * 2] = make_float2(pax[j], pay[j]);
        }
    }
}

// ---------------- layer-1 gather-combine, split in two halves ----------------
__global__ void k_l1i(float* __restrict__ out) {
    int t = blockIdx.x * blockDim.x + threadIdx.x;
    if (t >= NUx * 4) return;
    int n = t >> 2, lane = t & 3;
    int b2 = g_rp[2][n], e2 = g_rp[2][n + 1];
    float4 c = make_float4(0.f, 0.f, 0.f, 0.f);
    for (int i = b2; i < e2; i++) {
        int s2 = __ldg(&g_col[2][i]);
        float4 v = ((const float4*)g_p_item)[(size_t)s2 * 4 + lane];
        c.x += v.x; c.y += v.y; c.z += v.z; c.w += v.w;
    }
    float i2 = 1.0f / (float)max(e2 - b2, 1);
    ((float4*)out)[t] = make_float4(c.x * i2, c.y * i2, c.z * i2, c.w * i2);
}
__global__ void k_l1u(float* __restrict__ out) {
    int t = blockIdx.x * blockDim.x + threadIdx.x;
    if (t >= NUx * 4) return;
    int n = t >> 2, lane = t & 3;
    int b0 = g_rp[0][n], e0 = g_rp[0][n + 1];
    float4 a = make_float4(0.f, 0.f, 0.f, 0.f);
    for (int i = b0; i < e0; i++) {
        int s0 = __ldg(&g_col[0][i]);
        float4 v = ((const float4*)g_p_user)[(size_t)s0 * 4 + lane];
        a.x += v.x; a.y += v.y; a.z += v.z; a.w += v.w;
    }
    float i0 = 1.0f / (float)max(e0 - b0, 1);
    float4 o = ((float4*)out)[t];
    ((float4*)out)[t] = make_float4(o.x + a.x * i0, o.y + a.y * i0,
                                    o.z + a.z * i0, o.w + a.w * i0);
}

// ---------------- launch ----------------
extern "C" void kernel_launch(void* const* d_in, const int* in_sizes, int n_in,
                              void* d_out, int out_size) {
    const float* embed_user = (const float*)d_in[0];
    const float* embed_item = (const float*)d_in[1];
    const int* src_uu = (const int*)d_in[2];
    const int* dst_uu = (const int*)d_in[3];
    const int* src_ui = (const int*)d_in[4];
    const int* dst_ui = (const int*)d_in[5];
    const int* src_iu = (const int*)d_in[6];
    const int* dst_iu = (const int*)d_in[7];
    const float* W0_uu = (const float*)d_in[8];
    const float* b0_uu = (const float*)d_in[9];
    const float* W0_ui = (const float*)d_in[10];
    const float* b0_ui = (const float*)d_in[11];
    const float* W0_iu = (const float*)d_in[12];
    const float* b0_iu = (const float*)d_in[13];
    const float* W1_uu = (const float*)d_in[14];
    const float* b1_uu = (const float*)d_in[15];
    const float* W1_iu = (const float*)d_in[18];
    const float* b1_iu = (const float*)d_in[19];

    float *p_user, *p_item;
    int* degs;
    __nv_bfloat16 *ah, *al, *wt;
    cudaGetSymbolAddress((void**)&p_user, g_p_user);
    cudaGetSymbolAddress((void**)&p_item, g_p_item);
    cudaGetSymbolAddress((void**)&degs, g_deg);
    cudaGetSymbolAddress((void**)&ah, g_Ah);
    cudaGetSymbolAddress((void**)&al, g_Al);
    cudaGetSymbolAddress((void**)&wt, g_Wt);

    static cudaStream_t s1 = 0, s2 = 0;
    static cudaEvent_t eF = 0, eW = 0, eC = 0, eA0 = 0, eA2 = 0, eLi = 0;
    static bool init_done = false;
    const int SMEM_G = 92224;
    if (!init_done) {
        cudaStreamCreateWithFlags(&s1, cudaStreamNonBlocking);
        cudaStreamCreateWithFlags(&s2, cudaStreamNonBlocking);
        cudaEventCreateWithFlags(&eF, cudaEventDisableTiming);
        cudaEventCreateWithFlags(&eW, cudaEventDisableTiming);
        cudaEventCreateWithFlags(&eC, cudaEventDisableTiming);
        cudaEventCreateWithFlags(&eA0, cudaEventDisableTiming);
        cudaEventCreateWithFlags(&eA2, cudaEventDisableTiming);
        cudaEventCreateWithFlags(&eLi, cudaEventDisableTiming);
        cudaFuncSetAttribute(k_hgemm<2>, cudaFuncAttributeMaxDynamicSharedMemorySize, SMEM_G);
        cudaFuncSetAttribute(k_hgemm<1>, cudaFuncAttributeMaxDynamicSharedMemorySize, SMEM_G);
        init_done = true;
    }

    // fork
    cudaEventRecord(eF, 0);
    cudaStreamWaitEvent(s1, eF, 0);
    cudaStreamWaitEvent(s2, eF, 0);

    // s1: weight conversion (tiny)
    k_wcvt<<<dim3(128, 3), 128, 0, s1>>>(W0_uu, W0_iu, W0_ui);
    cudaEventRecord(eW, s1);

    // s0: batched CSR build (all 3 etypes), then agg0
    k_zero_small<<<NB, 256>>>();
    k_degree<<<EB, 256>>>(dst_uu, dst_ui, dst_iu);
    k_scan1<<<dim3(NB, 3), 256>>>();
    k_scan2<<<3, 512>>>();
    k_scan3<<<dim3(NB, 3), 256>>>();
    k_fill<<<dim3(EB, 3), 256>>>(src_uu, dst_uu, src_ui, dst_ui, src_iu, dst_iu);
    cudaEventRecord(eC, 0);
    k_agg<<<(NP + 7) / 8, 256>>>(0, (const float4*)embed_user);
    cudaEventRecord(eA0, 0);

    // s2: agg2 concurrent with agg0
    cudaStreamWaitEvent(s2, eC, 0);
    k_agg<<<(NP + 7) / 8, 256, 0, s2>>>(2, (const float4*)embed_item);
    cudaEventRecord(eA2, s2);

    const __nv_bfloat16* Ah0 = ah;
    const __nv_bfloat16* Ah1 = ah + (size_t)NP * D;
    const __nv_bfloat16* Ah2 = ah + (size_t)2 * NP * D;
    const __nv_bfloat16* Al0 = al;
    const __nv_bfloat16* Al1 = al + (size_t)NP * D;
    const __nv_bfloat16* Al2 = al + (size_t)2 * NP * D;
    const __nv_bfloat16* WhUU = wt;
    const __nv_bfloat16* WlUU = wt + 16384;
    const __nv_bfloat16* WhIU = wt + 2 * 16384;
    const __nv_bfloat16* WlIU = wt + 3 * 16384;
    const __nv_bfloat16* WhUI = wt + 4 * 16384;
    const __nv_bfloat16* WlUI = wt + 5 * 16384;

    // user GEMM on s0: needs agg0 (s0), agg2, weights
    cudaStreamWaitEvent(0, eW, 0);
    cudaStreamWaitEvent(0, eA2, 0);
    GP gu;
    gu.Ah[0] = Ah0; gu.Ah[1] = Ah2; gu.Al[0] = Al0; gu.Al[1] = Al2;
    gu.Wh[0] = WhUU; gu.Wh[1] = WhIU; gu.Wl[0] = WlUU; gu.Wl[1] = WlIU;
    gu.b0 = b0_uu; gu.b1 = b0_iu;
    gu.dg0 = degs; gu.dg1 = degs + 2 * NP;
    gu.W1 = W1_uu; gu.pb = b1_uu;
    gu.P = p_user; gu.N = NUx;
    k_hgemm<2><<<NP / 128, 256, SMEM_G>>>(gu);

    // s1: deferred agg1, item GEMM, l1i — hidden under user GEMM
    cudaStreamWaitEvent(s1, eA0, 0);
    cudaStreamWaitEvent(s1, eA2, 0);
    k_agg<<<(NP + 7) / 8, 256, 0, s1>>>(1, (const float4*)embed_user);
    GP gi;
    gi.Ah[0] = Ah1; gi.Ah[1] = Ah1; gi.Al[0] = Al1; gi.Al[1] = Al1;
    gi.Wh[0] = WhUI; gi.Wh[1] = WhUI; gi.Wl[0] = WlUI; gi.Wl[1] = WlUI;
    gi.b0 = b0_ui; gi.b1 = b0_ui;
    gi.dg0 = degs + NP; gi.dg1 = degs + NP;
    gi.W1 = W1_iu; gi.pb = b1_iu;
    gi.P = p_item; gi.N = NIx;
    k_hgemm<1><<<NP / 128, 256, SMEM_G, s1>>>(gi);
    k_l1i<<<(NUx * 4 + 255) / 256, 256, 0, s1>>>((float*)d_out);
    cudaEventRecord(eLi, s1);

    // critical-path tail
    cudaStreamWaitEvent(0, eLi, 0);
    k_l1u<<<(NUx * 4 + 255) / 256, 256>>>((float*)d_out);
}